// round 7
// baseline (speedup 1.0000x reference)
#include <cuda_runtime.h>
#include <cuda_bf16.h>
#include <math.h>
#include <stdint.h>

#define BB 4
#define SS 2048
#define DD 2048
typedef __nv_bfloat16 bf16;

constexpr int BM = 128, BN = 256, BK = 32;
constexpr int ROWB = 80;                     // 32 bf16 (64B) + 16B pad
constexpr int A_TILE = 128 * ROWB;           // 10240
constexpr int B_TILE = 256 * ROWB;           // 20480
constexpr int OFF_AH = 0;
constexpr int OFF_AL = OFF_AH + A_TILE;      // 10240
constexpr int OFF_BH = OFF_AL + A_TILE;      // 20480
constexpr int OFF_BL = OFF_BH + B_TILE;      // 40960
constexpr int STAGE = OFF_BL + B_TILE;       // 61440
constexpr int NSTAGE = 3;
constexpr int SMEM_TOTAL = NSTAGE * STAGE;   // 184320

// ---------------------------------------------------------------------------
// Scratch (device globals — no allocations allowed)
// ---------------------------------------------------------------------------
__device__ float g_Q [(size_t)BB * SS * DD];
__device__ float g_K [(size_t)BB * SS * DD];
__device__ float g_P [(size_t)BB * SS * SS];
__device__ float g_invf[DD / 2];

__device__ bf16 g_xh [(size_t)BB * SS * DD], g_xl [(size_t)BB * SS * DD];
__device__ bf16 g_Wqh[(size_t)DD * DD],      g_Wql[(size_t)DD * DD];
__device__ bf16 g_Wkh[(size_t)DD * DD],      g_Wkl[(size_t)DD * DD];
__device__ bf16 g_Wvh[(size_t)DD * DD],      g_Wvl[(size_t)DD * DD];
__device__ bf16 g_Woh[(size_t)DD * DD],      g_Wol[(size_t)DD * DD];
__device__ bf16 g_Qh [(size_t)BB * SS * DD], g_Ql [(size_t)BB * SS * DD];
__device__ bf16 g_Kh [(size_t)BB * SS * DD], g_Kl [(size_t)BB * SS * DD];
__device__ bf16 g_Vth[(size_t)BB * SS * DD], g_Vtl[(size_t)BB * SS * DD];  // [b][d][s]
__device__ bf16 g_Ph [(size_t)BB * SS * SS], g_Pl [(size_t)BB * SS * SS];
__device__ bf16 g_Ch [(size_t)BB * SS * DD], g_Cl [(size_t)BB * SS * DD];

// ---------------------------------------------------------------------------
// helpers
// ---------------------------------------------------------------------------
__device__ __forceinline__ uint32_t smem_u32(const void* p)
{
    uint32_t a;
    asm("{ .reg .u64 t; cvta.to.shared.u64 t, %1; cvt.u32.u64 %0, t; }"
        : "=r"(a) : "l"(p));
    return a;
}
__device__ __forceinline__ void cp16(uint32_t saddr, const void* g)
{
    asm volatile("cp.async.cg.shared.global [%0], [%1], 16;" :: "r"(saddr), "l"(g));
}
__device__ __forceinline__ void cp_commit() { asm volatile("cp.async.commit_group;"); }
__device__ __forceinline__ void cp_wait1()  { asm volatile("cp.async.wait_group 1;"); }
__device__ __forceinline__ void cp_wait0()  { asm volatile("cp.async.wait_group 0;"); }

__device__ __forceinline__ void ldsm4(uint32_t* r, uint32_t addr)
{
    asm volatile("ldmatrix.sync.aligned.m8n8.x4.shared.b16 {%0,%1,%2,%3}, [%4];\n"
                 : "=r"(r[0]), "=r"(r[1]), "=r"(r[2]), "=r"(r[3]) : "r"(addr));
}
__device__ __forceinline__ void mma16816(float* d, const uint32_t* a, const uint32_t* b)
{
    asm volatile(
        "mma.sync.aligned.m16n8k16.row.col.f32.bf16.bf16.f32 "
        "{%0,%1,%2,%3}, {%4,%5,%6,%7}, {%8,%9}, {%0,%1,%2,%3};\n"
        : "+f"(d[0]), "+f"(d[1]), "+f"(d[2]), "+f"(d[3])
        : "r"(a[0]), "r"(a[1]), "r"(a[2]), "r"(a[3]), "r"(b[0]), "r"(b[1]));
}
__device__ __forceinline__ void split1(float v, bf16& h, bf16& l)
{
    h = __float2bfloat16(v);
    l = __float2bfloat16(v - __bfloat162float(h));
}

// ---------------------------------------------------------------------------
// Pre-split bf16 GEMM (3-stage cp.async, 512 threads, 128x256 tile):
//   C[m,n] = sum_k A[m,k]*B[n,k];  acc = Ah*Bh + Ah*Bl + Al*Bh.
// EPI: 0 = fp32 C (+bias/scale/causal-zero), 1 = split bf16 (Ch,Cl),
//      2 = split + transpose per batch (Vt), with bias.
// ---------------------------------------------------------------------------
template <int EPI>
__global__ __launch_bounds__(512, 1) void gemm_pre(
    const bf16* __restrict__ Ah, const bf16* __restrict__ Al,
    const bf16* __restrict__ Bh, const bf16* __restrict__ Bl,
    const float* __restrict__ bias, float* __restrict__ C,
    bf16* __restrict__ Ch, bf16* __restrict__ Cl,
    int N, int K, long long sA, long long sB, long long sC,
    float scale, int causal, int triK)
{
    extern __shared__ __align__(128) char dsm[];
    const uint32_t smem_base = smem_u32(dsm);

    const int b = blockIdx.z;
    Ah += (long long)b * sA;  Al += (long long)b * sA;
    Bh += (long long)b * sB;  Bl += (long long)b * sB;
    if (EPI == 0) C += (long long)b * sC;
    if (EPI == 1) { Ch += (long long)b * sC; Cl += (long long)b * sC; }

    const int m0 = blockIdx.y * BM;
    const int n0 = blockIdx.x * BN;
    if (causal && n0 > m0 + BM - 1) return;
    const int kEnd = triK ? (m0 + BM) : K;
    const int nSteps = kEnd / BK;

    const int t = threadIdx.x;
    const int lane = t & 31, warp = t >> 5;
    const int wm = warp >> 2;   // 0..3 -> 32-row strip
    const int wn = warp & 3;    // 0..3 -> 64-col strip

    float acc[2][8][4];
#pragma unroll
    for (int i = 0; i < 2; i++)
#pragma unroll
        for (int j = 0; j < 8; j++)
#pragma unroll
            for (int q = 0; q < 4; q++) acc[i][j][q] = 0.f;

    // fill one stage: 3072 16B chunks, 6 per thread (each p-slice uniform)
    const int f_row = t >> 2;          // 0..127
    const int f_ch = t & 3;            // 0..3
    auto fill = [&](int buf, int ks) {
        const int k0 = ks * BK;
        const uint32_t sb = smem_base + buf * STAGE;
        const uint32_t so = (uint32_t)(f_row * ROWB + f_ch * 16);
        const long long gro = (long long)f_row * K + k0 + f_ch * 8;
        cp16(sb + OFF_AH + so, Ah + (long long)m0 * K + gro);
        cp16(sb + OFF_AL + so, Al + (long long)m0 * K + gro);
        cp16(sb + OFF_BH + so, Bh + (long long)n0 * K + gro);
        cp16(sb + OFF_BH + 128 * ROWB + so, Bh + (long long)(n0 + 128) * K + gro);
        cp16(sb + OFF_BL + so, Bl + (long long)n0 * K + gro);
        cp16(sb + OFF_BL + 128 * ROWB + so, Bl + (long long)(n0 + 128) * K + gro);
    };

    // ldmatrix lane->element offsets (validated layout, unchanged)
    const int a_r = (lane & 7) + ((lane >> 3) & 1) * 8;
    const int a_c = (lane >> 4) * 8;
    const int b_r = (lane & 7) + ((lane >> 4) & 1) * 8;
    const int b_c = ((lane >> 3) & 1) * 8;

    fill(0, 0); cp_commit();
    fill(1, 1); cp_commit();

    int buf = 0;
    for (int ks = 0; ks < nSteps; ks++) {
        cp_wait1();
        __syncthreads();                       // single barrier per k-step

        // prefetch stage ks+2 into buffer (ks+2)%3 — distinct from the compute
        // buffer (ks%3) and the in-flight one ((ks+1)%3); the barrier above
        // guarantees every warp is done reading it (last read at ks-1).
        {
            int nb = buf + 2; if (nb >= 3) nb -= 3;
            if (ks + 2 < nSteps) fill(nb, ks + 2);
            cp_commit();                       // commit even if empty: keeps
        }                                      // wait_group accounting exact

        const uint32_t sb = smem_base + buf * STAGE;
        const uint32_t bAh = sb + OFF_AH, bAl = sb + OFF_AL;
        const uint32_t bBh = sb + OFF_BH, bBl = sb + OFF_BL;

#pragma unroll
        for (int kk = 0; kk < BK; kk += 16) {
            uint32_t ah[2][4], al[2][4];
#pragma unroll
            for (int mt = 0; mt < 2; mt++) {
                const int row = wm * 32 + mt * 16 + a_r;
                const uint32_t off = (uint32_t)(row * ROWB + (kk + a_c) * 2);
                ldsm4(ah[mt], bAh + off);
                ldsm4(al[mt], bAl + off);
            }
#pragma unroll
            for (int np = 0; np < 4; np++) {
                const int nrow = wn * 64 + np * 16 + b_r;
                const uint32_t off = (uint32_t)(nrow * ROWB + (kk + b_c) * 2);
                uint32_t bh[4], bl[4];
                ldsm4(bh, bBh + off);
                ldsm4(bl, bBl + off);
#pragma unroll
                for (int mt = 0; mt < 2; mt++) {
                    mma16816(acc[mt][2 * np],     ah[mt], bh);
                    mma16816(acc[mt][2 * np],     ah[mt], bl);
                    mma16816(acc[mt][2 * np],     al[mt], bh);
                    mma16816(acc[mt][2 * np + 1], ah[mt], bh + 2);
                    mma16816(acc[mt][2 * np + 1], ah[mt], bl + 2);
                    mma16816(acc[mt][2 * np + 1], al[mt], bh + 2);
                }
            }
        }
        if (++buf == 3) buf = 0;
    }

    // ---------------- epilogue ----------------
    if (EPI == 2) {
        cp_wait0();
        __syncthreads();
        bf16* Th = reinterpret_cast<bf16*>(dsm);              // [256][136]
        bf16* Tl = Th + 256 * 136;
#pragma unroll
        for (int mt = 0; mt < 2; mt++) {
            const int li0 = wm * 32 + mt * 16 + (lane >> 2);
#pragma unroll
            for (int nt = 0; nt < 8; nt++) {
                const int lj = wn * 64 + nt * 8 + (lane & 3) * 2;
#pragma unroll
                for (int h = 0; h < 2; h++) {
                    const int li = li0 + h * 8;
#pragma unroll
                    for (int c = 0; c < 2; c++) {
                        float v = acc[mt][nt][h * 2 + c];
                        if (bias) v += bias[n0 + lj + c];
                        bf16 hh, ll;
                        split1(v, hh, ll);
                        Th[(lj + c) * 136 + li] = hh;
                        Tl[(lj + c) * 136 + li] = ll;
                    }
                }
            }
        }
        __syncthreads();
        {
            const int arr = t >> 8;          // 0 = hi, 1 = lo
            const int j = t & 255;           // local n (= d) row
            const int bb = m0 >> 11;         // SS = 2048
            const int s0 = m0 & (SS - 1);
            const bf16* src = (arr ? Tl : Th) + j * 136;
            bf16* dst = (arr ? Cl : Ch) + ((long long)bb * DD + n0 + j) * SS + s0;
#pragma unroll
            for (int i = 0; i < 128; i += 8)
                *reinterpret_cast<uint4*>(dst + i) =
                    *reinterpret_cast<const uint4*>(src + i);
        }
        return;
    }

#pragma unroll
    for (int mt = 0; mt < 2; mt++) {
        const int gi0 = m0 + wm * 32 + mt * 16 + (lane >> 2);
#pragma unroll
        for (int nt = 0; nt < 8; nt++) {
            const int gj = n0 + wn * 64 + nt * 8 + (lane & 3) * 2;
            const float* d = acc[mt][nt];
#pragma unroll
            for (int h = 0; h < 2; h++) {
                const int gi = gi0 + h * 8;
                float v0 = d[h * 2 + 0] * scale;
                float v1 = d[h * 2 + 1] * scale;
                if (bias) { v0 += bias[gj]; v1 += bias[gj + 1]; }
                if (causal) {
                    if (gj > gi) v0 = 0.f;
                    if (gj + 1 > gi) v1 = 0.f;
                }
                if (EPI == 0) {
                    *reinterpret_cast<float2*>(&C[(long long)gi * N + gj]) =
                        make_float2(v0, v1);
                } else {
                    bf16 h0, l0, h1, l1;
                    split1(v0, h0, l0);
                    split1(v1, h1, l1);
                    __nv_bfloat162 ph; ph.x = h0; ph.y = h1;
                    __nv_bfloat162 pl; pl.x = l0; pl.y = l1;
                    *reinterpret_cast<__nv_bfloat162*>(&Ch[(long long)gi * N + gj]) = ph;
                    *reinterpret_cast<__nv_bfloat162*>(&Cl[(long long)gi * N + gj]) = pl;
                }
            }
        }
    }
}

// ---------------------------------------------------------------------------
__global__ void split_kernel(const float* __restrict__ src,
                             bf16* __restrict__ dh, bf16* __restrict__ dl,
                             long long n4)
{
    const long long i = (long long)blockIdx.x * blockDim.x + threadIdx.x;
    if (i >= n4) return;
    float4 v = *reinterpret_cast<const float4*>(src + i * 4);
    bf16 h[4], l[4];
    split1(v.x, h[0], l[0]); split1(v.y, h[1], l[1]);
    split1(v.z, h[2], l[2]); split1(v.w, h[3], l[3]);
    *reinterpret_cast<uint2*>(dh + i * 4) = *reinterpret_cast<uint2*>(h);
    *reinterpret_cast<uint2*>(dl + i * 4) = *reinterpret_cast<uint2*>(l);
}

// ---------------------------------------------------------------------------
__global__ void invf_kernel(float* __restrict__ invf)
{
    const int i = blockIdx.x * blockDim.x + threadIdx.x;
    if (i < DD / 2)
        invf[i] = (float)exp(-(double)i * (9.210340371976184 / (double)(DD / 2)));
}

// ---------------------------------------------------------------------------
__global__ void rope_split_kernel(const float* __restrict__ Q,
                                  const float* __restrict__ Kt,
                                  const float* __restrict__ invf,
                                  bf16* __restrict__ Qh, bf16* __restrict__ Ql,
                                  bf16* __restrict__ Kh, bf16* __restrict__ Kl)
{
    const int half = DD / 2;
    long long idx = (long long)blockIdx.x * blockDim.x + threadIdx.x;
    const long long total = (long long)BB * SS * half;
    if (idx >= total) return;

    const int i = (int)(idx % half);
    const long long bs = idx / half;
    const int s = (int)(bs % SS);

    const float ang = (float)s * invf[i];
    float sn, cs;
    sincosf(ang, &sn, &cs);

    const long long o = bs * DD;
    const float q1 = Q[o + i], q2 = Q[o + i + half];
    const float k1 = Kt[o + i], k2 = Kt[o + i + half];
    const float qa = q1 * cs - q2 * sn, qb = q1 * sn + q2 * cs;
    const float ka = k1 * cs - k2 * sn, kb = k1 * sn + k2 * cs;

    bf16 h, l;
    split1(qa, h, l); Qh[o + i] = h;        Ql[o + i] = l;
    split1(qb, h, l); Qh[o + i + half] = h; Ql[o + i + half] = l;
    split1(ka, h, l); Kh[o + i] = h;        Kl[o + i] = l;
    split1(kb, h, l); Kh[o + i + half] = h; Kl[o + i + half] = l;
}

// ---------------------------------------------------------------------------
__inline__ __device__ float warpMax(float v)
{
    for (int o = 16; o; o >>= 1) v = fmaxf(v, __shfl_xor_sync(0xffffffffu, v, o));
    return v;
}
__inline__ __device__ float warpSum(float v)
{
    for (int o = 16; o; o >>= 1) v += __shfl_xor_sync(0xffffffffu, v, o);
    return v;
}

__global__ __launch_bounds__(256) void softmax_split_kernel(
    const float* __restrict__ P, bf16* __restrict__ Ph, bf16* __restrict__ Pl)
{
    const int i = blockIdx.x;
    const int b = blockIdx.y;
    const long long off = ((long long)b * SS + i) * SS;
    const float* row = P + off;
    const int len = i + 1;
    const int t = threadIdx.x;
    const int lane = t & 31, w = t >> 5;

    __shared__ float sh[8];
    __shared__ float s_bcast;

    float m = -INFINITY;
    for (int j = t; j < len; j += 256) m = fmaxf(m, row[j]);
    m = warpMax(m);
    if (lane == 0) sh[w] = m;
    __syncthreads();
    if (t == 0) {
        float mm = sh[0];
        for (int k = 1; k < 8; k++) mm = fmaxf(mm, sh[k]);
        s_bcast = mm;
    }
    __syncthreads();
    m = s_bcast;
    __syncthreads();

    float sum = 0.f;
    for (int j = t; j < len; j += 256) sum += expf(row[j] - m);
    sum = warpSum(sum);
    if (lane == 0) sh[w] = sum;
    __syncthreads();
    if (t == 0) {
        float ss = 0.f;
        for (int k = 0; k < 8; k++) ss += sh[k];
        s_bcast = ss;
    }
    __syncthreads();
    const float inv = 1.f / s_bcast;

    for (int j = t; j < len; j += 256) {
        bf16 h, l;
        split1(expf(row[j] - m) * inv, h, l);
        Ph[off + j] = h;
        Pl[off + j] = l;
    }
    const int kend = ((i >> 7) + 1) << 7;
    const bf16 z = __float2bfloat16(0.f);
    for (int j = len + t; j < kend; j += 256) { Ph[off + j] = z; Pl[off + j] = z; }
}

// ---------------------------------------------------------------------------
extern "C" void kernel_launch(void* const* d_in, const int* in_sizes, int n_in,
                              void* d_out, int out_size)
{
    const float* x  = (const float*)d_in[0];
    // d_in[1] = mask — analytic
    const float* Wq = (const float*)d_in[2];
    const float* bq = (const float*)d_in[3];
    const float* Wk = (const float*)d_in[4];
    const float* bk = (const float*)d_in[5];
    const float* Wv = (const float*)d_in[6];
    const float* bv = (const float*)d_in[7];
    const float* Wo = (const float*)d_in[8];
    const float* bo = (const float*)d_in[9];
    float* out = (float*)d_out;

    float *pQ, *pK, *pP, *pInvf;
    cudaGetSymbolAddress((void**)&pQ, g_Q);
    cudaGetSymbolAddress((void**)&pK, g_K);
    cudaGetSymbolAddress((void**)&pP, g_P);
    cudaGetSymbolAddress((void**)&pInvf, g_invf);

    bf16 *xh, *xl, *Wqh, *Wql, *Wkh, *Wkl, *Wvh, *Wvl, *Woh, *Wol;
    bf16 *Qh, *Ql, *Kh, *Kl, *Vth, *Vtl, *Ph, *Pl, *Chh, *Cll;
    cudaGetSymbolAddress((void**)&xh, g_xh);   cudaGetSymbolAddress((void**)&xl, g_xl);
    cudaGetSymbolAddress((void**)&Wqh, g_Wqh); cudaGetSymbolAddress((void**)&Wql, g_Wql);
    cudaGetSymbolAddress((void**)&Wkh, g_Wkh); cudaGetSymbolAddress((void**)&Wkl, g_Wkl);
    cudaGetSymbolAddress((void**)&Wvh, g_Wvh); cudaGetSymbolAddress((void**)&Wvl, g_Wvl);
    cudaGetSymbolAddress((void**)&Woh, g_Woh); cudaGetSymbolAddress((void**)&Wol, g_Wol);
    cudaGetSymbolAddress((void**)&Qh, g_Qh);   cudaGetSymbolAddress((void**)&Ql, g_Ql);
    cudaGetSymbolAddress((void**)&Kh, g_Kh);   cudaGetSymbolAddress((void**)&Kl, g_Kl);
    cudaGetSymbolAddress((void**)&Vth, g_Vth); cudaGetSymbolAddress((void**)&Vtl, g_Vtl);
    cudaGetSymbolAddress((void**)&Ph, g_Ph);   cudaGetSymbolAddress((void**)&Pl, g_Pl);
    cudaGetSymbolAddress((void**)&Chh, g_Ch);  cudaGetSymbolAddress((void**)&Cll, g_Cl);

    cudaFuncSetAttribute(gemm_pre<0>, cudaFuncAttributeMaxDynamicSharedMemorySize, SMEM_TOTAL);
    cudaFuncSetAttribute(gemm_pre<1>, cudaFuncAttributeMaxDynamicSharedMemorySize, SMEM_TOTAL);
    cudaFuncSetAttribute(gemm_pre<2>, cudaFuncAttributeMaxDynamicSharedMemorySize, SMEM_TOTAL);

    const dim3 blk(512);
    const dim3 gProj(DD / BN, (BB * SS) / BM, 1);   // 8 x 64
    const dim3 gAttn(SS / BN, SS / BM, BB);         // 8 x 16 x 4

    invf_kernel<<<(DD / 2 + 255) / 256, 256>>>(pInvf);

    // 0) pre-split x and weights
    {
        const long long nx4 = (long long)BB * SS * DD / 4;
        split_kernel<<<(int)((nx4 + 255) / 256), 256>>>(x, xh, xl, nx4);
        const long long nw4 = (long long)DD * DD / 4;
        const int gw = (int)((nw4 + 255) / 256);
        split_kernel<<<gw, 256>>>(Wq, Wqh, Wql, nw4);
        split_kernel<<<gw, 256>>>(Wk, Wkh, Wkl, nw4);
        split_kernel<<<gw, 256>>>(Wv, Wvh, Wvl, nw4);
        split_kernel<<<gw, 256>>>(Wo, Woh, Wol, nw4);
    }

    // 1) projections
    gemm_pre<0><<<gProj, blk, SMEM_TOTAL>>>(xh, xl, Wqh, Wql, bq, pQ, nullptr, nullptr,
                                            DD, DD, 0, 0, 0, 1.f, 0, 0);
    gemm_pre<0><<<gProj, blk, SMEM_TOTAL>>>(xh, xl, Wkh, Wkl, bk, pK, nullptr, nullptr,
                                            DD, DD, 0, 0, 0, 1.f, 0, 0);
    gemm_pre<2><<<gProj, blk, SMEM_TOTAL>>>(xh, xl, Wvh, Wvl, bv, nullptr, Vth, Vtl,
                                            DD, DD, 0, 0, 0, 1.f, 0, 0);

    // 2) RoPE + split Q/K
    {
        const long long total = (long long)BB * SS * (DD / 2);
        rope_split_kernel<<<(int)((total + 255) / 256), 256>>>(pQ, pK, pInvf,
                                                               Qh, Ql, Kh, Kl);
    }

    // 3) scores = Q K^T / sqrt(D), causal -> fp32 P
    const float scale = 0.022097086912079608f;  // 1/sqrt(2048)
    gemm_pre<0><<<gAttn, blk, SMEM_TOTAL>>>(Qh, Ql, Kh, Kl, nullptr, pP, nullptr, nullptr,
                                            SS, DD, (long long)SS * DD, (long long)SS * DD,
                                            (long long)SS * SS, scale, 1, 0);

    // 4) softmax -> split P (+zero-fill)
    softmax_split_kernel<<<dim3(SS, BB), 256>>>(pP, Ph, Pl);

    // 5) ctx = P V (triangular K) -> split ctx
    gemm_pre<1><<<gAttn, blk, SMEM_TOTAL>>>(Ph, Pl, Vth, Vtl, nullptr, nullptr, Chh, Cll,
                                            DD, SS, (long long)SS * SS, (long long)SS * DD,
                                            (long long)SS * DD, 1.f, 0, 1);

    // 6) out = ctx Wo^T + bo
    gemm_pre<0><<<gProj, blk, SMEM_TOTAL>>>(Chh, Cll, Woh, Wol, bo, out, nullptr, nullptr,
                                            DD, DD, 0, 0, 0, 1.f, 0, 0);
}

// round 9
// speedup vs baseline: 1.1004x; 1.1004x over previous
#include <cuda_runtime.h>
#include <cuda_bf16.h>
#include <math.h>
#include <stdint.h>

#define BB 4
#define SS 2048
#define DD 2048
typedef __nv_bfloat16 bf16;

constexpr int BM = 128, BN = 128, BK = 32;
constexpr int ROWB = 80;                    // bytes per smem row (32 bf16 + 16B pad)
constexpr int TILE_B = 128 * ROWB;          // 10240 bytes per sub-tile
constexpr int STAGE = 4 * TILE_B;           // Ah, Al, Bh, Bl
constexpr int SMEM_TOTAL = 2 * STAGE;       // 81920

// ---------------------------------------------------------------------------
// Scratch (device globals — no allocations allowed)
// ---------------------------------------------------------------------------
__device__ float g_Q [(size_t)BB * SS * DD];
__device__ float g_K [(size_t)BB * SS * DD];
__device__ float g_invf[DD / 2];

__device__ bf16 g_xh [(size_t)BB * SS * DD], g_xl [(size_t)BB * SS * DD];
__device__ bf16 g_Wqh[(size_t)DD * DD],      g_Wql[(size_t)DD * DD];
__device__ bf16 g_Wkh[(size_t)DD * DD],      g_Wkl[(size_t)DD * DD];
__device__ bf16 g_Wvh[(size_t)DD * DD],      g_Wvl[(size_t)DD * DD];
__device__ bf16 g_Woh[(size_t)DD * DD],      g_Wol[(size_t)DD * DD];
__device__ bf16 g_Qh [(size_t)BB * SS * DD], g_Ql [(size_t)BB * SS * DD];
__device__ bf16 g_Kh [(size_t)BB * SS * DD], g_Kl [(size_t)BB * SS * DD];
__device__ bf16 g_Vth[(size_t)BB * SS * DD], g_Vtl[(size_t)BB * SS * DD];  // [b][d][s]
__device__ bf16 g_Ph [(size_t)BB * SS * SS], g_Pl [(size_t)BB * SS * SS];
__device__ bf16 g_Ch [(size_t)BB * SS * DD], g_Cl [(size_t)BB * SS * DD];

// ---------------------------------------------------------------------------
// helpers
// ---------------------------------------------------------------------------
__device__ __forceinline__ uint32_t smem_u32(const void* p)
{
    uint32_t a;
    asm("{ .reg .u64 t; cvta.to.shared.u64 t, %1; cvt.u32.u64 %0, t; }"
        : "=r"(a) : "l"(p));
    return a;
}
__device__ __forceinline__ void cp16(uint32_t saddr, const void* g)
{
    asm volatile("cp.async.cg.shared.global [%0], [%1], 16;" :: "r"(saddr), "l"(g));
}
__device__ __forceinline__ void cp_commit() { asm volatile("cp.async.commit_group;"); }
__device__ __forceinline__ void cp_wait1()  { asm volatile("cp.async.wait_group 1;"); }
__device__ __forceinline__ void cp_wait0()  { asm volatile("cp.async.wait_group 0;"); }

__device__ __forceinline__ void ldsm4(uint32_t* r, uint32_t addr)
{
    asm volatile("ldmatrix.sync.aligned.m8n8.x4.shared.b16 {%0,%1,%2,%3}, [%4];\n"
                 : "=r"(r[0]), "=r"(r[1]), "=r"(r[2]), "=r"(r[3]) : "r"(addr));
}
__device__ __forceinline__ void mma16816(float* d, const uint32_t* a, const uint32_t* b)
{
    asm volatile(
        "mma.sync.aligned.m16n8k16.row.col.f32.bf16.bf16.f32 "
        "{%0,%1,%2,%3}, {%4,%5,%6,%7}, {%8,%9}, {%0,%1,%2,%3};\n"
        : "+f"(d[0]), "+f"(d[1]), "+f"(d[2]), "+f"(d[3])
        : "r"(a[0]), "r"(a[1]), "r"(a[2]), "r"(a[3]), "r"(b[0]), "r"(b[1]));
}
__device__ __forceinline__ void split1(float v, bf16& h, bf16& l)
{
    h = __float2bfloat16(v);
    l = __float2bfloat16(v - __bfloat162float(h));
}

// ---------------------------------------------------------------------------
// Pre-split bf16 GEMM (R5 configuration: 256 thr, 2 CTAs/SM, 2-stage cp.async):
//   C[m,n] = sum_k A[m,k]*B[n,k];  acc = Ah*Bh + Ah*Bl + Al*Bh.
// EPI: 0 = fp32 C (+bias/scale/causal-zero), 1 = split bf16 (Ch,Cl),
//      2 = split + transpose per batch (Vt), with bias.
// ---------------------------------------------------------------------------
template <int EPI>
__global__ __launch_bounds__(256, 2) void gemm_pre(
    const bf16* __restrict__ Ah, const bf16* __restrict__ Al,
    const bf16* __restrict__ Bh, const bf16* __restrict__ Bl,
    const float* __restrict__ bias, float* __restrict__ C,
    bf16* __restrict__ Ch, bf16* __restrict__ Cl,
    int N, int K, long long sA, long long sB, long long sC,
    float scale, int causal, int triK)
{
    extern __shared__ __align__(128) char dsm[];
    const uint32_t smem_base = smem_u32(dsm);

    const int b = blockIdx.z;
    Ah += (long long)b * sA;  Al += (long long)b * sA;
    Bh += (long long)b * sB;  Bl += (long long)b * sB;
    if (EPI == 0) C += (long long)b * sC;
    if (EPI == 1) { Ch += (long long)b * sC; Cl += (long long)b * sC; }

    const int m0 = blockIdx.y * BM;
    const int n0 = blockIdx.x * BN;
    if (causal && n0 > m0 + BM - 1) return;
    const int kEnd = triK ? (m0 + BM) : K;
    const int nSteps = kEnd / BK;

    const int t = threadIdx.x;
    const int lane = t & 31, warp = t >> 5;
    const int wm = warp >> 1;   // 0..3 -> 32 rows
    const int wn = warp & 1;    // 0..1 -> 64 cols

    float acc[2][8][4];
#pragma unroll
    for (int i = 0; i < 2; i++)
#pragma unroll
        for (int j = 0; j < 8; j++)
#pragma unroll
            for (int q = 0; q < 4; q++) acc[i][j][q] = 0.f;

    auto fill = [&](int buf, int ks) {
        const int k0 = ks * BK;
        const uint32_t sb = smem_base + buf * STAGE;
#pragma unroll
        for (int p = 0; p < 2; p++) {
            const int idx = p * 256 + t;
            const int row = idx >> 2;
            const int ch = idx & 3;
            const uint32_t so = (uint32_t)(row * ROWB + ch * 16);
            const long long ga = (long long)(m0 + row) * K + k0 + ch * 8;
            const long long gb = (long long)(n0 + row) * K + k0 + ch * 8;
            cp16(sb + 0 * TILE_B + so, Ah + ga);
            cp16(sb + 1 * TILE_B + so, Al + ga);
            cp16(sb + 2 * TILE_B + so, Bh + gb);
            cp16(sb + 3 * TILE_B + so, Bl + gb);
        }
    };

    const int a_r = (lane & 7) + ((lane >> 3) & 1) * 8;
    const int a_c = (lane >> 4) * 8;
    const int b_r = (lane & 7) + ((lane >> 4) & 1) * 8;
    const int b_c = ((lane >> 3) & 1) * 8;

    fill(0, 0); cp_commit();
    fill(1, 1); cp_commit();

    for (int ks = 0; ks < nSteps; ks++) {
        cp_wait1();
        __syncthreads();

        const uint32_t sb = smem_base + (ks & 1) * STAGE;
        const uint32_t bAh = sb, bAl = sb + TILE_B;
        const uint32_t bBh = sb + 2 * TILE_B, bBl = sb + 3 * TILE_B;

#pragma unroll
        for (int kk = 0; kk < BK; kk += 16) {
            uint32_t ah[2][4], al[2][4];
#pragma unroll
            for (int mt = 0; mt < 2; mt++) {
                const int row = wm * 32 + mt * 16 + a_r;
                const uint32_t off = (uint32_t)(row * ROWB + (kk + a_c) * 2);
                ldsm4(ah[mt], bAh + off);
                ldsm4(al[mt], bAl + off);
            }
#pragma unroll
            for (int np = 0; np < 4; np++) {
                const int nrow = wn * 64 + np * 16 + b_r;
                const uint32_t off = (uint32_t)(nrow * ROWB + (kk + b_c) * 2);
                uint32_t bh[4], bl[4];
                ldsm4(bh, bBh + off);
                ldsm4(bl, bBl + off);
#pragma unroll
                for (int mt = 0; mt < 2; mt++) {
                    mma16816(acc[mt][2 * np],     ah[mt], bh);
                    mma16816(acc[mt][2 * np],     ah[mt], bl);
                    mma16816(acc[mt][2 * np],     al[mt], bh);
                    mma16816(acc[mt][2 * np + 1], ah[mt], bh + 2);
                    mma16816(acc[mt][2 * np + 1], ah[mt], bl + 2);
                    mma16816(acc[mt][2 * np + 1], al[mt], bh + 2);
                }
            }
        }
        __syncthreads();
        if (ks + 2 < nSteps) fill(ks & 1, ks + 2);
        cp_commit();
    }

    // ---------------- epilogue ----------------
    if (EPI == 2) {
        cp_wait0();
        __syncthreads();
        bf16* Th = reinterpret_cast<bf16*>(dsm);              // [128][136]
        bf16* Tl = Th + 128 * 136;
#pragma unroll
        for (int mt = 0; mt < 2; mt++) {
            const int li0 = wm * 32 + mt * 16 + (lane >> 2);
#pragma unroll
            for (int nt = 0; nt < 8; nt++) {
                const int lj = wn * 64 + nt * 8 + (lane & 3) * 2;
#pragma unroll
                for (int h = 0; h < 2; h++) {
                    const int li = li0 + h * 8;
#pragma unroll
                    for (int c = 0; c < 2; c++) {
                        float v = acc[mt][nt][h * 2 + c];
                        if (bias) v += bias[n0 + lj + c];
                        bf16 hh, ll;
                        split1(v, hh, ll);
                        Th[(lj + c) * 136 + li] = hh;
                        Tl[(lj + c) * 136 + li] = ll;
                    }
                }
            }
        }
        __syncthreads();
        {
            const int arr = t >> 7;          // 0 = hi, 1 = lo
            const int j = t & 127;           // local n (= d) row
            const int bb = m0 >> 11;         // SS = 2048
            const int s0 = m0 & (SS - 1);
            const bf16* src = (arr ? Tl : Th) + j * 136;
            bf16* dst = (arr ? Cl : Ch) + ((long long)bb * DD + n0 + j) * SS + s0;
#pragma unroll
            for (int i = 0; i < 128; i += 8)
                *reinterpret_cast<uint4*>(dst + i) =
                    *reinterpret_cast<const uint4*>(src + i);
        }
        return;
    }

#pragma unroll
    for (int mt = 0; mt < 2; mt++) {
        const int gi0 = m0 + wm * 32 + mt * 16 + (lane >> 2);
#pragma unroll
        for (int nt = 0; nt < 8; nt++) {
            const int gj = n0 + wn * 64 + nt * 8 + (lane & 3) * 2;
            const float* d = acc[mt][nt];
#pragma unroll
            for (int h = 0; h < 2; h++) {
                const int gi = gi0 + h * 8;
                float v0 = d[h * 2 + 0] * scale;
                float v1 = d[h * 2 + 1] * scale;
                if (bias) { v0 += bias[gj]; v1 += bias[gj + 1]; }
                if (causal) {
                    if (gj > gi) v0 = 0.f;
                    if (gj + 1 > gi) v1 = 0.f;
                }
                if (EPI == 0) {
                    *reinterpret_cast<float2*>(&C[(long long)gi * N + gj]) =
                        make_float2(v0, v1);
                } else {
                    bf16 h0, l0, h1, l1;
                    split1(v0, h0, l0);
                    split1(v1, h1, l1);
                    __nv_bfloat162 ph; ph.x = h0; ph.y = h1;
                    __nv_bfloat162 pl; pl.x = l0; pl.y = l1;
                    *reinterpret_cast<__nv_bfloat162*>(&Ch[(long long)gi * N + gj]) = ph;
                    *reinterpret_cast<__nv_bfloat162*>(&Cl[(long long)gi * N + gj]) = pl;
                }
            }
        }
    }
}

// ---------------------------------------------------------------------------
__global__ void split_kernel(const float* __restrict__ src,
                             bf16* __restrict__ dh, bf16* __restrict__ dl,
                             long long n4)
{
    const long long i = (long long)blockIdx.x * blockDim.x + threadIdx.x;
    if (i >= n4) return;
    float4 v = *reinterpret_cast<const float4*>(src + i * 4);
    bf16 h[4], l[4];
    split1(v.x, h[0], l[0]); split1(v.y, h[1], l[1]);
    split1(v.z, h[2], l[2]); split1(v.w, h[3], l[3]);
    *reinterpret_cast<uint2*>(dh + i * 4) = *reinterpret_cast<uint2*>(h);
    *reinterpret_cast<uint2*>(dl + i * 4) = *reinterpret_cast<uint2*>(l);
}

// ---------------------------------------------------------------------------
__global__ void invf_kernel(float* __restrict__ invf)
{
    const int i = blockIdx.x * blockDim.x + threadIdx.x;
    if (i < DD / 2)
        invf[i] = (float)exp(-(double)i * (9.210340371976184 / (double)(DD / 2)));
}

// ---------------------------------------------------------------------------
__global__ void rope_split_kernel(const float* __restrict__ Q,
                                  const float* __restrict__ Kt,
                                  const float* __restrict__ invf,
                                  bf16* __restrict__ Qh, bf16* __restrict__ Ql,
                                  bf16* __restrict__ Kh, bf16* __restrict__ Kl)
{
    const int half = DD / 2;
    long long idx = (long long)blockIdx.x * blockDim.x + threadIdx.x;
    const long long total = (long long)BB * SS * half;
    if (idx >= total) return;

    const int i = (int)(idx % half);
    const long long bs = idx / half;
    const int s = (int)(bs % SS);

    const float ang = (float)s * invf[i];
    float sn, cs;
    sincosf(ang, &sn, &cs);

    const long long o = bs * DD;
    const float q1 = Q[o + i], q2 = Q[o + i + half];
    const float k1 = Kt[o + i], k2 = Kt[o + i + half];
    const float qa = q1 * cs - q2 * sn, qb = q1 * sn + q2 * cs;
    const float ka = k1 * cs - k2 * sn, kb = k1 * sn + k2 * cs;

    bf16 h, l;
    split1(qa, h, l); Qh[o + i] = h;        Ql[o + i] = l;
    split1(qb, h, l); Qh[o + i + half] = h; Ql[o + i + half] = l;
    split1(ka, h, l); Kh[o + i] = h;        Kl[o + i] = l;
    split1(kb, h, l); Kh[o + i + half] = h; Kl[o + i + half] = l;
}

// ---------------------------------------------------------------------------
// Register-resident causal softmax over split-bf16 scores (in place).
// The above-diagonal range [len, 128-aligned) is already split-zero from the
// causal GEMM epilogue, so no zero-fill pass is needed.
// ---------------------------------------------------------------------------
__inline__ __device__ float warpMax(float v)
{
    for (int o = 16; o; o >>= 1) v = fmaxf(v, __shfl_xor_sync(0xffffffffu, v, o));
    return v;
}
__inline__ __device__ float warpSum(float v)
{
    for (int o = 16; o; o >>= 1) v += __shfl_xor_sync(0xffffffffu, v, o);
    return v;
}

__global__ __launch_bounds__(256) void softmax_split_kernel(
    bf16* __restrict__ Ph, bf16* __restrict__ Pl)
{
    const int i = blockIdx.x;
    const int b = blockIdx.y;
    const long long off = ((long long)b * SS + i) * SS;
    const int len = i + 1;
    const int t = threadIdx.x;
    const int lane = t & 31, w = t >> 5;

    __shared__ float sh[8];
    __shared__ float s_bcast;

    // load into registers (<= 8 elements per thread), reconstruct fp32
    float s[8];
    float m = -INFINITY;
#pragma unroll
    for (int p = 0; p < 8; p++) {
        const int j = t + p * 256;
        if (j < len) {
            s[p] = __bfloat162float(Ph[off + j]) + __bfloat162float(Pl[off + j]);
            m = fmaxf(m, s[p]);
        }
    }
    m = warpMax(m);
    if (lane == 0) sh[w] = m;
    __syncthreads();
    if (t == 0) {
        float mm = sh[0];
        for (int k = 1; k < 8; k++) mm = fmaxf(mm, sh[k]);
        s_bcast = mm;
    }
    __syncthreads();
    m = s_bcast;
    __syncthreads();

    float sum = 0.f;
#pragma unroll
    for (int p = 0; p < 8; p++) {
        const int j = t + p * 256;
        if (j < len) {
            s[p] = expf(s[p] - m);
            sum += s[p];
        }
    }
    sum = warpSum(sum);
    if (lane == 0) sh[w] = sum;
    __syncthreads();
    if (t == 0) {
        float ss = 0.f;
        for (int k = 0; k < 8; k++) ss += sh[k];
        s_bcast = ss;
    }
    __syncthreads();
    const float inv = 1.f / s_bcast;

#pragma unroll
    for (int p = 0; p < 8; p++) {
        const int j = t + p * 256;
        if (j < len) {
            bf16 h, l;
            split1(s[p] * inv, h, l);
            Ph[off + j] = h;
            Pl[off + j] = l;
        }
    }
}

// ---------------------------------------------------------------------------
extern "C" void kernel_launch(void* const* d_in, const int* in_sizes, int n_in,
                              void* d_out, int out_size)
{
    const float* x  = (const float*)d_in[0];
    // d_in[1] = mask — analytic
    const float* Wq = (const float*)d_in[2];
    const float* bq = (const float*)d_in[3];
    const float* Wk = (const float*)d_in[4];
    const float* bk = (const float*)d_in[5];
    const float* Wv = (const float*)d_in[6];
    const float* bv = (const float*)d_in[7];
    const float* Wo = (const float*)d_in[8];
    const float* bo = (const float*)d_in[9];
    float* out = (float*)d_out;

    float *pQ, *pK, *pInvf;
    cudaGetSymbolAddress((void**)&pQ, g_Q);
    cudaGetSymbolAddress((void**)&pK, g_K);
    cudaGetSymbolAddress((void**)&pInvf, g_invf);

    bf16 *xh, *xl, *Wqh, *Wql, *Wkh, *Wkl, *Wvh, *Wvl, *Woh, *Wol;
    bf16 *Qh, *Ql, *Kh, *Kl, *Vth, *Vtl, *Ph, *Pl, *Chh, *Cll;
    cudaGetSymbolAddress((void**)&xh, g_xh);   cudaGetSymbolAddress((void**)&xl, g_xl);
    cudaGetSymbolAddress((void**)&Wqh, g_Wqh); cudaGetSymbolAddress((void**)&Wql, g_Wql);
    cudaGetSymbolAddress((void**)&Wkh, g_Wkh); cudaGetSymbolAddress((void**)&Wkl, g_Wkl);
    cudaGetSymbolAddress((void**)&Wvh, g_Wvh); cudaGetSymbolAddress((void**)&Wvl, g_Wvl);
    cudaGetSymbolAddress((void**)&Woh, g_Woh); cudaGetSymbolAddress((void**)&Wol, g_Wol);
    cudaGetSymbolAddress((void**)&Qh, g_Qh);   cudaGetSymbolAddress((void**)&Ql, g_Ql);
    cudaGetSymbolAddress((void**)&Kh, g_Kh);   cudaGetSymbolAddress((void**)&Kl, g_Kl);
    cudaGetSymbolAddress((void**)&Vth, g_Vth); cudaGetSymbolAddress((void**)&Vtl, g_Vtl);
    cudaGetSymbolAddress((void**)&Ph, g_Ph);   cudaGetSymbolAddress((void**)&Pl, g_Pl);
    cudaGetSymbolAddress((void**)&Chh, g_Ch);  cudaGetSymbolAddress((void**)&Cll, g_Cl);

    cudaFuncSetAttribute(gemm_pre<0>, cudaFuncAttributeMaxDynamicSharedMemorySize, SMEM_TOTAL);
    cudaFuncSetAttribute(gemm_pre<1>, cudaFuncAttributeMaxDynamicSharedMemorySize, SMEM_TOTAL);
    cudaFuncSetAttribute(gemm_pre<2>, cudaFuncAttributeMaxDynamicSharedMemorySize, SMEM_TOTAL);

    const dim3 blk(256);
    const dim3 gProj(DD / BN, (BB * SS) / BM, 1);
    const dim3 gAttn(SS / BN, SS / BM, BB);

    invf_kernel<<<(DD / 2 + 255) / 256, 256>>>(pInvf);

    // 0) pre-split x and weights
    {
        const long long nx4 = (long long)BB * SS * DD / 4;
        split_kernel<<<(int)((nx4 + 255) / 256), 256>>>(x, xh, xl, nx4);
        const long long nw4 = (long long)DD * DD / 4;
        const int gw = (int)((nw4 + 255) / 256);
        split_kernel<<<gw, 256>>>(Wq, Wqh, Wql, nw4);
        split_kernel<<<gw, 256>>>(Wk, Wkh, Wkl, nw4);
        split_kernel<<<gw, 256>>>(Wv, Wvh, Wvl, nw4);
        split_kernel<<<gw, 256>>>(Wo, Woh, Wol, nw4);
    }

    // 1) projections: Q,K -> fp32 (rope consumes); V -> split+transposed
    gemm_pre<0><<<gProj, blk, SMEM_TOTAL>>>(xh, xl, Wqh, Wql, bq, pQ, nullptr, nullptr,
                                            DD, DD, 0, 0, 0, 1.f, 0, 0);
    gemm_pre<0><<<gProj, blk, SMEM_TOTAL>>>(xh, xl, Wkh, Wkl, bk, pK, nullptr, nullptr,
                                            DD, DD, 0, 0, 0, 1.f, 0, 0);
    gemm_pre<2><<<gProj, blk, SMEM_TOTAL>>>(xh, xl, Wvh, Wvl, bv, nullptr, Vth, Vtl,
                                            DD, DD, 0, 0, 0, 1.f, 0, 0);

    // 2) RoPE + split Q/K
    {
        const long long total = (long long)BB * SS * (DD / 2);
        rope_split_kernel<<<(int)((total + 255) / 256), 256>>>(pQ, pK, pInvf,
                                                               Qh, Ql, Kh, Kl);
    }

    // 3) scores = Q K^T / sqrt(D), causal -> split bf16 P directly (no fp32 P)
    const float scale = 0.022097086912079608f;  // 1/sqrt(2048)
    gemm_pre<1><<<gAttn, blk, SMEM_TOTAL>>>(Qh, Ql, Kh, Kl, nullptr, nullptr, Ph, Pl,
                                            SS, DD, (long long)SS * DD, (long long)SS * DD,
                                            (long long)SS * SS, scale, 1, 0);

    // 4) register softmax on split P (in place)
    softmax_split_kernel<<<dim3(SS, BB), 256>>>(Ph, Pl);

    // 5) ctx = P V (triangular K) -> split ctx
    gemm_pre<1><<<gAttn, blk, SMEM_TOTAL>>>(Ph, Pl, Vth, Vtl, nullptr, nullptr, Chh, Cll,
                                            DD, SS, (long long)SS * SS, (long long)SS * DD,
                                            (long long)SS * DD, 1.f, 0, 1);

    // 6) out = ctx Wo^T + bo
    gemm_pre<0><<<gProj, blk, SMEM_TOTAL>>>(Chh, Cll, Woh, Wol, bo, out, nullptr, nullptr,
                                            DD, DD, 0, 0, 0, 1.f, 0, 0);
}

// round 10
// speedup vs baseline: 1.1108x; 1.0094x over previous
#include <cuda_runtime.h>
#include <cuda_bf16.h>
#include <math.h>
#include <stdint.h>

#define BB 4
#define SS 2048
#define DD 2048
typedef __nv_bfloat16 bf16;

constexpr int BM = 128, BN = 128, BK = 32;
constexpr int ROWB = 80;                    // bytes per smem row (32 bf16 + 16B pad)
constexpr int TILE_B = 128 * ROWB;          // 10240 bytes per sub-tile
constexpr int STAGE = 4 * TILE_B;           // Ah, Al, Bh, Bl
constexpr int SMEM_TOTAL = 2 * STAGE;       // 81920

// ---------------------------------------------------------------------------
// Scratch (device globals — no allocations allowed)
// ---------------------------------------------------------------------------
__device__ float g_Q [(size_t)BB * SS * DD];
__device__ float g_K [(size_t)BB * SS * DD];
__device__ float g_invf[DD / 2];

__device__ bf16 g_xh [(size_t)BB * SS * DD], g_xl [(size_t)BB * SS * DD];
__device__ bf16 g_Wqh[(size_t)DD * DD],      g_Wql[(size_t)DD * DD];
__device__ bf16 g_Wkh[(size_t)DD * DD],      g_Wkl[(size_t)DD * DD];
__device__ bf16 g_Wvh[(size_t)DD * DD],      g_Wvl[(size_t)DD * DD];
__device__ bf16 g_Woh[(size_t)DD * DD],      g_Wol[(size_t)DD * DD];
__device__ bf16 g_Qh [(size_t)BB * SS * DD], g_Ql [(size_t)BB * SS * DD];
__device__ bf16 g_Kh [(size_t)BB * SS * DD], g_Kl [(size_t)BB * SS * DD];
__device__ bf16 g_Vth[(size_t)BB * SS * DD], g_Vtl[(size_t)BB * SS * DD];  // [b][d][s]
__device__ bf16 g_Ph [(size_t)BB * SS * SS], g_Pl [(size_t)BB * SS * SS];
__device__ bf16 g_Ch [(size_t)BB * SS * DD], g_Cl [(size_t)BB * SS * DD];

// ---------------------------------------------------------------------------
// helpers
// ---------------------------------------------------------------------------
__device__ __forceinline__ uint32_t smem_u32(const void* p)
{
    uint32_t a;
    asm("{ .reg .u64 t; cvta.to.shared.u64 t, %1; cvt.u32.u64 %0, t; }"
        : "=r"(a) : "l"(p));
    return a;
}
__device__ __forceinline__ void cp16(uint32_t saddr, const void* g)
{
    asm volatile("cp.async.cg.shared.global [%0], [%1], 16;" :: "r"(saddr), "l"(g));
}
__device__ __forceinline__ void cp_commit() { asm volatile("cp.async.commit_group;"); }
__device__ __forceinline__ void cp_wait1()  { asm volatile("cp.async.wait_group 1;"); }
__device__ __forceinline__ void cp_wait0()  { asm volatile("cp.async.wait_group 0;"); }

__device__ __forceinline__ void ldsm4(uint32_t* r, uint32_t addr)
{
    asm volatile("ldmatrix.sync.aligned.m8n8.x4.shared.b16 {%0,%1,%2,%3}, [%4];\n"
                 : "=r"(r[0]), "=r"(r[1]), "=r"(r[2]), "=r"(r[3]) : "r"(addr));
}
__device__ __forceinline__ void mma16816(float* d, const uint32_t* a, const uint32_t* b)
{
    asm volatile(
        "mma.sync.aligned.m16n8k16.row.col.f32.bf16.bf16.f32 "
        "{%0,%1,%2,%3}, {%4,%5,%6,%7}, {%8,%9}, {%0,%1,%2,%3};\n"
        : "+f"(d[0]), "+f"(d[1]), "+f"(d[2]), "+f"(d[3])
        : "r"(a[0]), "r"(a[1]), "r"(a[2]), "r"(a[3]), "r"(b[0]), "r"(b[1]));
}
__device__ __forceinline__ void split1(float v, bf16& h, bf16& l)
{
    h = __float2bfloat16(v);
    l = __float2bfloat16(v - __bfloat162float(h));
}

// ---------------------------------------------------------------------------
// Pre-split bf16 GEMM body (256 thr, 2 CTAs/SM, 2-stage cp.async):
//   C[m,n] = sum_k A[m,k]*B[n,k];  acc = Ah*Bh + Ah*Bl + Al*Bh.
// EPI: 0 = fp32 C (+bias/scale/causal-zero), 1 = split bf16 (Ch,Cl),
//      2 = split + transpose per batch (Vt), with bias.
// ---------------------------------------------------------------------------
template <int EPI>
__device__ __forceinline__ void gemm_body(
    const bf16* __restrict__ Ah, const bf16* __restrict__ Al,
    const bf16* __restrict__ Bh, const bf16* __restrict__ Bl,
    const float* __restrict__ bias, float* __restrict__ C,
    bf16* __restrict__ Ch, bf16* __restrict__ Cl,
    int N, int K, float scale, int causal, int triK,
    int m0, int n0, char* dsm)
{
    const uint32_t smem_base = smem_u32(dsm);

    if (causal && n0 > m0 + BM - 1) return;
    const int kEnd = triK ? (m0 + BM) : K;
    const int nSteps = kEnd / BK;

    const int t = threadIdx.x;
    const int lane = t & 31, warp = t >> 5;
    const int wm = warp >> 1;   // 0..3 -> 32 rows
    const int wn = warp & 1;    // 0..1 -> 64 cols

    float acc[2][8][4];
#pragma unroll
    for (int i = 0; i < 2; i++)
#pragma unroll
        for (int j = 0; j < 8; j++)
#pragma unroll
            for (int q = 0; q < 4; q++) acc[i][j][q] = 0.f;

    auto fill = [&](int buf, int ks) {
        const int k0 = ks * BK;
        const uint32_t sb = smem_base + buf * STAGE;
#pragma unroll
        for (int p = 0; p < 2; p++) {
            const int idx = p * 256 + t;
            const int row = idx >> 2;
            const int ch = idx & 3;
            const uint32_t so = (uint32_t)(row * ROWB + ch * 16);
            const long long ga = (long long)(m0 + row) * K + k0 + ch * 8;
            const long long gb = (long long)(n0 + row) * K + k0 + ch * 8;
            cp16(sb + 0 * TILE_B + so, Ah + ga);
            cp16(sb + 1 * TILE_B + so, Al + ga);
            cp16(sb + 2 * TILE_B + so, Bh + gb);
            cp16(sb + 3 * TILE_B + so, Bl + gb);
        }
    };

    const int a_r = (lane & 7) + ((lane >> 3) & 1) * 8;
    const int a_c = (lane >> 4) * 8;
    const int b_r = (lane & 7) + ((lane >> 4) & 1) * 8;
    const int b_c = ((lane >> 3) & 1) * 8;

    fill(0, 0); cp_commit();
    fill(1, 1); cp_commit();

    for (int ks = 0; ks < nSteps; ks++) {
        cp_wait1();
        __syncthreads();

        const uint32_t sb = smem_base + (ks & 1) * STAGE;
        const uint32_t bAh = sb, bAl = sb + TILE_B;
        const uint32_t bBh = sb + 2 * TILE_B, bBl = sb + 3 * TILE_B;

#pragma unroll
        for (int kk = 0; kk < BK; kk += 16) {
            uint32_t ah[2][4], al[2][4];
#pragma unroll
            for (int mt = 0; mt < 2; mt++) {
                const int row = wm * 32 + mt * 16 + a_r;
                const uint32_t off = (uint32_t)(row * ROWB + (kk + a_c) * 2);
                ldsm4(ah[mt], bAh + off);
                ldsm4(al[mt], bAl + off);
            }
#pragma unroll
            for (int np = 0; np < 4; np++) {
                const int nrow = wn * 64 + np * 16 + b_r;
                const uint32_t off = (uint32_t)(nrow * ROWB + (kk + b_c) * 2);
                uint32_t bh[4], bl[4];
                ldsm4(bh, bBh + off);
                ldsm4(bl, bBl + off);
#pragma unroll
                for (int mt = 0; mt < 2; mt++) {
                    mma16816(acc[mt][2 * np],     ah[mt], bh);
                    mma16816(acc[mt][2 * np],     ah[mt], bl);
                    mma16816(acc[mt][2 * np],     al[mt], bh);
                    mma16816(acc[mt][2 * np + 1], ah[mt], bh + 2);
                    mma16816(acc[mt][2 * np + 1], ah[mt], bl + 2);
                    mma16816(acc[mt][2 * np + 1], al[mt], bh + 2);
                }
            }
        }
        __syncthreads();
        if (ks + 2 < nSteps) fill(ks & 1, ks + 2);
        cp_commit();
    }

    // ---------------- epilogue ----------------
    if (EPI == 2) {
        cp_wait0();
        __syncthreads();
        bf16* Th = reinterpret_cast<bf16*>(dsm);              // [128][136]
        bf16* Tl = Th + 128 * 136;
#pragma unroll
        for (int mt = 0; mt < 2; mt++) {
            const int li0 = wm * 32 + mt * 16 + (lane >> 2);
#pragma unroll
            for (int nt = 0; nt < 8; nt++) {
                const int lj = wn * 64 + nt * 8 + (lane & 3) * 2;
#pragma unroll
                for (int h = 0; h < 2; h++) {
                    const int li = li0 + h * 8;
#pragma unroll
                    for (int c = 0; c < 2; c++) {
                        float v = acc[mt][nt][h * 2 + c];
                        if (bias) v += bias[n0 + lj + c];
                        bf16 hh, ll;
                        split1(v, hh, ll);
                        Th[(lj + c) * 136 + li] = hh;
                        Tl[(lj + c) * 136 + li] = ll;
                    }
                }
            }
        }
        __syncthreads();
        {
            const int arr = t >> 7;          // 0 = hi, 1 = lo
            const int j = t & 127;           // local n (= d) row
            const int bb = m0 >> 11;         // SS = 2048
            const int s0 = m0 & (SS - 1);
            const bf16* src = (arr ? Tl : Th) + j * 136;
            bf16* dst = (arr ? Cl : Ch) + ((long long)bb * DD + n0 + j) * SS + s0;
#pragma unroll
            for (int i = 0; i < 128; i += 8)
                *reinterpret_cast<uint4*>(dst + i) =
                    *reinterpret_cast<const uint4*>(src + i);
        }
        return;
    }

#pragma unroll
    for (int mt = 0; mt < 2; mt++) {
        const int gi0 = m0 + wm * 32 + mt * 16 + (lane >> 2);
#pragma unroll
        for (int nt = 0; nt < 8; nt++) {
            const int gj = n0 + wn * 64 + nt * 8 + (lane & 3) * 2;
            const float* d = acc[mt][nt];
#pragma unroll
            for (int h = 0; h < 2; h++) {
                const int gi = gi0 + h * 8;
                float v0 = d[h * 2 + 0] * scale;
                float v1 = d[h * 2 + 1] * scale;
                if (bias) { v0 += bias[gj]; v1 += bias[gj + 1]; }
                if (causal) {
                    if (gj > gi) v0 = 0.f;
                    if (gj + 1 > gi) v1 = 0.f;
                }
                if (EPI == 0) {
                    *reinterpret_cast<float2*>(&C[(long long)gi * N + gj]) =
                        make_float2(v0, v1);
                } else {
                    bf16 h0, l0, h1, l1;
                    split1(v0, h0, l0);
                    split1(v1, h1, l1);
                    __nv_bfloat162 ph; ph.x = h0; ph.y = h1;
                    __nv_bfloat162 pl; pl.x = l0; pl.y = l1;
                    *reinterpret_cast<__nv_bfloat162*>(&Ch[(long long)gi * N + gj]) = ph;
                    *reinterpret_cast<__nv_bfloat162*>(&Cl[(long long)gi * N + gj]) = pl;
                }
            }
        }
    }
}

// ---------------------------------------------------------------------------
// Merged Q/K/V projection: grid z selects projection (0=Q fp32, 1=K fp32,
// 2=V split+transposed).
// ---------------------------------------------------------------------------
__global__ __launch_bounds__(256, 2) void proj3_kernel(
    const bf16* __restrict__ xh, const bf16* __restrict__ xl,
    const bf16* __restrict__ Wqh, const bf16* __restrict__ Wql,
    const float* __restrict__ bq, float* __restrict__ Q,
    const bf16* __restrict__ Wkh, const bf16* __restrict__ Wkl,
    const float* __restrict__ bk, float* __restrict__ Kt,
    const bf16* __restrict__ Wvh, const bf16* __restrict__ Wvl,
    const float* __restrict__ bv, bf16* __restrict__ Vth, bf16* __restrict__ Vtl)
{
    extern __shared__ __align__(128) char dsm[];
    const int m0 = blockIdx.y * BM;
    const int n0 = blockIdx.x * BN;
    const int z = blockIdx.z;
    if (z == 0)
        gemm_body<0>(xh, xl, Wqh, Wql, bq, Q, nullptr, nullptr,
                     DD, DD, 1.f, 0, 0, m0, n0, dsm);
    else if (z == 1)
        gemm_body<0>(xh, xl, Wkh, Wkl, bk, Kt, nullptr, nullptr,
                     DD, DD, 1.f, 0, 0, m0, n0, dsm);
    else
        gemm_body<2>(xh, xl, Wvh, Wvl, bv, nullptr, Vth, Vtl,
                     DD, DD, 1.f, 0, 0, m0, n0, dsm);
}

// scores = Q K^T / sqrt(D), causal, split-bf16 output; batch on z
__global__ __launch_bounds__(256, 2) void scores_kernel(
    const bf16* __restrict__ Qh, const bf16* __restrict__ Ql,
    const bf16* __restrict__ Kh, const bf16* __restrict__ Kl,
    bf16* __restrict__ Ph, bf16* __restrict__ Pl, float scale)
{
    extern __shared__ __align__(128) char dsm[];
    const long long zd = (long long)blockIdx.z * SS * DD;
    const long long zs = (long long)blockIdx.z * SS * SS;
    gemm_body<1>(Qh + zd, Ql + zd, Kh + zd, Kl + zd, nullptr, nullptr,
                 Ph + zs, Pl + zs, SS, DD, scale, 1, 0,
                 blockIdx.y * BM, blockIdx.x * BN, dsm);
}

// ctx = P V (triangular K limit), split-bf16 output; batch on z
__global__ __launch_bounds__(256, 2) void pv_kernel(
    const bf16* __restrict__ Ph, const bf16* __restrict__ Pl,
    const bf16* __restrict__ Vth, const bf16* __restrict__ Vtl,
    bf16* __restrict__ Ch, bf16* __restrict__ Cl)
{
    extern __shared__ __align__(128) char dsm[];
    const long long zs = (long long)blockIdx.z * SS * SS;
    const long long zd = (long long)blockIdx.z * SS * DD;
    gemm_body<1>(Ph + zs, Pl + zs, Vth + zd, Vtl + zd, nullptr, nullptr,
                 Ch + zd, Cl + zd, DD, SS, 1.f, 0, 1,
                 blockIdx.y * BM, blockIdx.x * BN, dsm);
}

// out = ctx Wo^T + bo (fp32 output)
__global__ __launch_bounds__(256, 2) void outproj_kernel(
    const bf16* __restrict__ Ch, const bf16* __restrict__ Cl,
    const bf16* __restrict__ Woh, const bf16* __restrict__ Wol,
    const float* __restrict__ bo, float* __restrict__ out)
{
    extern __shared__ __align__(128) char dsm[];
    gemm_body<0>(Ch, Cl, Woh, Wol, bo, out, nullptr, nullptr,
                 DD, DD, 1.f, 0, 0, blockIdx.y * BM, blockIdx.x * BN, dsm);
}

// ---------------------------------------------------------------------------
// Fused split: x|Wq|Wk|Wv|Wo -> bf16 hi/lo in one launch; also fills invf.
// ---------------------------------------------------------------------------
constexpr long long N4X = (long long)BB * SS * DD / 4;   // 4,194,304
constexpr long long N4W = (long long)DD * DD / 4;        // 1,048,576

__global__ void split_all_kernel(
    const float* __restrict__ x,
    const float* __restrict__ Wq, const float* __restrict__ Wk,
    const float* __restrict__ Wv, const float* __restrict__ Wo,
    bf16* __restrict__ xh, bf16* __restrict__ xl,
    bf16* __restrict__ Wqh, bf16* __restrict__ Wql,
    bf16* __restrict__ Wkh, bf16* __restrict__ Wkl,
    bf16* __restrict__ Wvh, bf16* __restrict__ Wvl,
    bf16* __restrict__ Woh, bf16* __restrict__ Wol,
    float* __restrict__ invf)
{
    const long long i = (long long)blockIdx.x * blockDim.x + threadIdx.x;
    if (i < DD / 2)
        invf[i] = (float)exp(-(double)i * (9.210340371976184 / (double)(DD / 2)));

    const float* src;
    bf16 *dh, *dl;
    long long o = i;
    if (i < N4X)                { src = x;  dh = xh;  dl = xl; }
    else if (i < N4X + N4W)     { src = Wq; dh = Wqh; dl = Wql; o = i - N4X; }
    else if (i < N4X + 2 * N4W) { src = Wk; dh = Wkh; dl = Wkl; o = i - N4X - N4W; }
    else if (i < N4X + 3 * N4W) { src = Wv; dh = Wvh; dl = Wvl; o = i - N4X - 2 * N4W; }
    else if (i < N4X + 4 * N4W) { src = Wo; dh = Woh; dl = Wol; o = i - N4X - 3 * N4W; }
    else return;

    float4 v = *reinterpret_cast<const float4*>(src + o * 4);
    bf16 h[4], l[4];
    split1(v.x, h[0], l[0]); split1(v.y, h[1], l[1]);
    split1(v.z, h[2], l[2]); split1(v.w, h[3], l[3]);
    *reinterpret_cast<uint2*>(dh + o * 4) = *reinterpret_cast<uint2*>(h);
    *reinterpret_cast<uint2*>(dl + o * 4) = *reinterpret_cast<uint2*>(l);
}

// ---------------------------------------------------------------------------
// RoPE: rotate fp32 Q/K pairs, emit bf16 hi/lo splits.
// ---------------------------------------------------------------------------
__global__ void rope_split_kernel(const float* __restrict__ Q,
                                  const float* __restrict__ Kt,
                                  const float* __restrict__ invf,
                                  bf16* __restrict__ Qh, bf16* __restrict__ Ql,
                                  bf16* __restrict__ Kh, bf16* __restrict__ Kl)
{
    const int half = DD / 2;
    long long idx = (long long)blockIdx.x * blockDim.x + threadIdx.x;
    const long long total = (long long)BB * SS * half;
    if (idx >= total) return;

    const int i = (int)(idx % half);
    const long long bs = idx / half;
    const int s = (int)(bs % SS);

    const float ang = (float)s * invf[i];
    float sn, cs;
    sincosf(ang, &sn, &cs);

    const long long o = bs * DD;
    const float q1 = Q[o + i], q2 = Q[o + i + half];
    const float k1 = Kt[o + i], k2 = Kt[o + i + half];
    const float qa = q1 * cs - q2 * sn, qb = q1 * sn + q2 * cs;
    const float ka = k1 * cs - k2 * sn, kb = k1 * sn + k2 * cs;

    bf16 h, l;
    split1(qa, h, l); Qh[o + i] = h;        Ql[o + i] = l;
    split1(qb, h, l); Qh[o + i + half] = h; Ql[o + i + half] = l;
    split1(ka, h, l); Kh[o + i] = h;        Kl[o + i] = l;
    split1(kb, h, l); Kh[o + i + half] = h; Kl[o + i + half] = l;
}

// ---------------------------------------------------------------------------
// Register-resident causal softmax over split-bf16 scores (in place).
// Above-diagonal range is already split-zero from the causal GEMM epilogue.
// ---------------------------------------------------------------------------
__inline__ __device__ float warpMax(float v)
{
    for (int o = 16; o; o >>= 1) v = fmaxf(v, __shfl_xor_sync(0xffffffffu, v, o));
    return v;
}
__inline__ __device__ float warpSum(float v)
{
    for (int o = 16; o; o >>= 1) v += __shfl_xor_sync(0xffffffffu, v, o);
    return v;
}

__global__ __launch_bounds__(256) void softmax_split_kernel(
    bf16* __restrict__ Ph, bf16* __restrict__ Pl)
{
    const int i = blockIdx.x;
    const int b = blockIdx.y;
    const long long off = ((long long)b * SS + i) * SS;
    const int len = i + 1;
    const int t = threadIdx.x;
    const int lane = t & 31, w = t >> 5;

    __shared__ float sh[8];
    __shared__ float s_bcast;

    float s[8];
    float m = -INFINITY;
#pragma unroll
    for (int p = 0; p < 8; p++) {
        const int j = t + p * 256;
        if (j < len) {
            s[p] = __bfloat162float(Ph[off + j]) + __bfloat162float(Pl[off + j]);
            m = fmaxf(m, s[p]);
        }
    }
    m = warpMax(m);
    if (lane == 0) sh[w] = m;
    __syncthreads();
    if (t == 0) {
        float mm = sh[0];
        for (int k = 1; k < 8; k++) mm = fmaxf(mm, sh[k]);
        s_bcast = mm;
    }
    __syncthreads();
    m = s_bcast;
    __syncthreads();

    float sum = 0.f;
#pragma unroll
    for (int p = 0; p < 8; p++) {
        const int j = t + p * 256;
        if (j < len) {
            s[p] = expf(s[p] - m);
            sum += s[p];
        }
    }
    sum = warpSum(sum);
    if (lane == 0) sh[w] = sum;
    __syncthreads();
    if (t == 0) {
        float ss = 0.f;
        for (int k = 0; k < 8; k++) ss += sh[k];
        s_bcast = ss;
    }
    __syncthreads();
    const float inv = 1.f / s_bcast;

#pragma unroll
    for (int p = 0; p < 8; p++) {
        const int j = t + p * 256;
        if (j < len) {
            bf16 h, l;
            split1(s[p] * inv, h, l);
            Ph[off + j] = h;
            Pl[off + j] = l;
        }
    }
}

// ---------------------------------------------------------------------------
extern "C" void kernel_launch(void* const* d_in, const int* in_sizes, int n_in,
                              void* d_out, int out_size)
{
    const float* x  = (const float*)d_in[0];
    // d_in[1] = mask — analytic
    const float* Wq = (const float*)d_in[2];
    const float* bq = (const float*)d_in[3];
    const float* Wk = (const float*)d_in[4];
    const float* bk = (const float*)d_in[5];
    const float* Wv = (const float*)d_in[6];
    const float* bv = (const float*)d_in[7];
    const float* Wo = (const float*)d_in[8];
    const float* bo = (const float*)d_in[9];
    float* out = (float*)d_out;

    float *pQ, *pK, *pInvf;
    cudaGetSymbolAddress((void**)&pQ, g_Q);
    cudaGetSymbolAddress((void**)&pK, g_K);
    cudaGetSymbolAddress((void**)&pInvf, g_invf);

    bf16 *xh, *xl, *Wqh, *Wql, *Wkh, *Wkl, *Wvh, *Wvl, *Woh, *Wol;
    bf16 *Qh, *Ql, *Kh, *Kl, *Vth, *Vtl, *Ph, *Pl, *Chh, *Cll;
    cudaGetSymbolAddress((void**)&xh, g_xh);   cudaGetSymbolAddress((void**)&xl, g_xl);
    cudaGetSymbolAddress((void**)&Wqh, g_Wqh); cudaGetSymbolAddress((void**)&Wql, g_Wql);
    cudaGetSymbolAddress((void**)&Wkh, g_Wkh); cudaGetSymbolAddress((void**)&Wkl, g_Wkl);
    cudaGetSymbolAddress((void**)&Wvh, g_Wvh); cudaGetSymbolAddress((void**)&Wvl, g_Wvl);
    cudaGetSymbolAddress((void**)&Woh, g_Woh); cudaGetSymbolAddress((void**)&Wol, g_Wol);
    cudaGetSymbolAddress((void**)&Qh, g_Qh);   cudaGetSymbolAddress((void**)&Ql, g_Ql);
    cudaGetSymbolAddress((void**)&Kh, g_Kh);   cudaGetSymbolAddress((void**)&Kl, g_Kl);
    cudaGetSymbolAddress((void**)&Vth, g_Vth); cudaGetSymbolAddress((void**)&Vtl, g_Vtl);
    cudaGetSymbolAddress((void**)&Ph, g_Ph);   cudaGetSymbolAddress((void**)&Pl, g_Pl);
    cudaGetSymbolAddress((void**)&Chh, g_Ch);  cudaGetSymbolAddress((void**)&Cll, g_Cl);

    cudaFuncSetAttribute(proj3_kernel,   cudaFuncAttributeMaxDynamicSharedMemorySize, SMEM_TOTAL);
    cudaFuncSetAttribute(scores_kernel,  cudaFuncAttributeMaxDynamicSharedMemorySize, SMEM_TOTAL);
    cudaFuncSetAttribute(pv_kernel,      cudaFuncAttributeMaxDynamicSharedMemorySize, SMEM_TOTAL);
    cudaFuncSetAttribute(outproj_kernel, cudaFuncAttributeMaxDynamicSharedMemorySize, SMEM_TOTAL);

    const dim3 blk(256);

    // 1) fused split of x and all weights (+ invf table)
    {
        const long long n4 = N4X + 4 * N4W;
        split_all_kernel<<<(int)((n4 + 255) / 256), 256>>>(
            x, Wq, Wk, Wv, Wo, xh, xl, Wqh, Wql, Wkh, Wkl, Wvh, Wvl, Woh, Wol, pInvf);
    }

    // 2) merged Q/K/V projections (one launch, 3072 CTAs)
    proj3_kernel<<<dim3(DD / BN, (BB * SS) / BM, 3), blk, SMEM_TOTAL>>>(
        xh, xl, Wqh, Wql, bq, pQ, Wkh, Wkl, bk, pK, Wvh, Wvl, bv, Vth, Vtl);

    // 3) RoPE + split Q/K
    {
        const long long total = (long long)BB * SS * (DD / 2);
        rope_split_kernel<<<(int)((total + 255) / 256), 256>>>(pQ, pK, pInvf,
                                                               Qh, Ql, Kh, Kl);
    }

    // 4) scores = Q K^T / sqrt(D), causal -> split bf16 P
    const float scale = 0.022097086912079608f;  // 1/sqrt(2048)
    scores_kernel<<<dim3(SS / BN, SS / BM, BB), blk, SMEM_TOTAL>>>(
        Qh, Ql, Kh, Kl, Ph, Pl, scale);

    // 5) register softmax on split P (in place)
    softmax_split_kernel<<<dim3(SS, BB), 256>>>(Ph, Pl);

    // 6) ctx = P V (triangular K) -> split ctx
    pv_kernel<<<dim3(DD / BN, SS / BM, BB), blk, SMEM_TOTAL>>>(
        Ph, Pl, Vth, Vtl, Chh, Cll);

    // 7) out = ctx Wo^T + bo
    outproj_kernel<<<dim3(DD / BN, (BB * SS) / BM, 1), blk, SMEM_TOTAL>>>(
        Chh, Cll, Woh, Wol, bo, out);
}

// round 11
// speedup vs baseline: 1.1246x; 1.0124x over previous
#include <cuda_runtime.h>
#include <cuda_bf16.h>
#include <math.h>
#include <stdint.h>

#define BB 4
#define SS 2048
#define DD 2048
typedef __nv_bfloat16 bf16;

constexpr int BM = 128, BN = 128, BK = 16;
constexpr int SUB_B = 128 * 32;             // one sub-tile: 128 rows x 16 bf16 (32B), swizzled
constexpr int STAGE = 4 * SUB_B;            // Ah, Al, Bh, Bl = 16 KB
constexpr int NSTAGE = 6;
constexpr int SMEM_TOTAL = NSTAGE * STAGE;  // 98304 (2 CTAs/SM)

// ---------------------------------------------------------------------------
// Scratch (device globals — no allocations allowed)
// ---------------------------------------------------------------------------
__device__ float g_Q [(size_t)BB * SS * DD];
__device__ float g_K [(size_t)BB * SS * DD];
__device__ float g_invf[DD / 2];

__device__ bf16 g_xh [(size_t)BB * SS * DD], g_xl [(size_t)BB * SS * DD];
__device__ bf16 g_Wqh[(size_t)DD * DD],      g_Wql[(size_t)DD * DD];
__device__ bf16 g_Wkh[(size_t)DD * DD],      g_Wkl[(size_t)DD * DD];
__device__ bf16 g_Wvh[(size_t)DD * DD],      g_Wvl[(size_t)DD * DD];
__device__ bf16 g_Woh[(size_t)DD * DD],      g_Wol[(size_t)DD * DD];
__device__ bf16 g_Qh [(size_t)BB * SS * DD], g_Ql [(size_t)BB * SS * DD];
__device__ bf16 g_Kh [(size_t)BB * SS * DD], g_Kl [(size_t)BB * SS * DD];
__device__ bf16 g_Vth[(size_t)BB * SS * DD], g_Vtl[(size_t)BB * SS * DD];  // [b][d][s]
__device__ bf16 g_Ph [(size_t)BB * SS * SS], g_Pl [(size_t)BB * SS * SS];
__device__ bf16 g_Ch [(size_t)BB * SS * DD], g_Cl [(size_t)BB * SS * DD];

// ---------------------------------------------------------------------------
// helpers
// ---------------------------------------------------------------------------
__device__ __forceinline__ uint32_t smem_u32(const void* p)
{
    uint32_t a;
    asm("{ .reg .u64 t; cvta.to.shared.u64 t, %1; cvt.u32.u64 %0, t; }"
        : "=r"(a) : "l"(p));
    return a;
}
__device__ __forceinline__ void cp16(uint32_t saddr, const void* g)
{
    asm volatile("cp.async.cg.shared.global [%0], [%1], 16;" :: "r"(saddr), "l"(g));
}
__device__ __forceinline__ void cp_commit() { asm volatile("cp.async.commit_group;"); }
__device__ __forceinline__ void cp_wait4()  { asm volatile("cp.async.wait_group 4;"); }
__device__ __forceinline__ void cp_wait0()  { asm volatile("cp.async.wait_group 0;"); }

__device__ __forceinline__ void ldsm4(uint32_t* r, uint32_t addr)
{
    asm volatile("ldmatrix.sync.aligned.m8n8.x4.shared.b16 {%0,%1,%2,%3}, [%4];\n"
                 : "=r"(r[0]), "=r"(r[1]), "=r"(r[2]), "=r"(r[3]) : "r"(addr));
}
__device__ __forceinline__ void mma16816(float* d, const uint32_t* a, const uint32_t* b)
{
    asm volatile(
        "mma.sync.aligned.m16n8k16.row.col.f32.bf16.bf16.f32 "
        "{%0,%1,%2,%3}, {%4,%5,%6,%7}, {%8,%9}, {%0,%1,%2,%3};\n"
        : "+f"(d[0]), "+f"(d[1]), "+f"(d[2]), "+f"(d[3])
        : "r"(a[0]), "r"(a[1]), "r"(a[2]), "r"(a[3]), "r"(b[0]), "r"(b[1]));
}
__device__ __forceinline__ void split1(float v, bf16& h, bf16& l)
{
    h = __float2bfloat16(v);
    l = __float2bfloat16(v - __bfloat162float(h));
}

// Swizzled smem byte offset within one sub-tile: row r (0..127), 16B chunk c16 (0..1).
// slot = c16 ^ ((r>>2)&1) keeps all 8 rows of an ldsm phase in distinct 16B banks.
__device__ __forceinline__ uint32_t swz_off(int r, int c16)
{
    return (uint32_t)(r * 32 + ((c16 ^ ((r >> 2) & 1)) << 4));
}

// ---------------------------------------------------------------------------
// Pre-split bf16 GEMM body (256 thr, 2 CTAs/SM, 6-stage BK=16 cp.async):
//   C[m,n] = sum_k A[m,k]*B[n,k];  acc = Ah*Bh + Ah*Bl + Al*Bh.
// EPI: 0 = fp32 C (+bias/scale/causal-zero), 1 = split bf16 (Ch,Cl),
//      2 = split + transpose per batch (Vt), with bias.
// ---------------------------------------------------------------------------
template <int EPI>
__device__ __forceinline__ void gemm_body(
    const bf16* __restrict__ Ah, const bf16* __restrict__ Al,
    const bf16* __restrict__ Bh, const bf16* __restrict__ Bl,
    const float* __restrict__ bias, float* __restrict__ C,
    bf16* __restrict__ Ch, bf16* __restrict__ Cl,
    int N, int K, float scale, int causal, int triK,
    int m0, int n0, char* dsm)
{
    const uint32_t smem_base = smem_u32(dsm);

    if (causal && n0 > m0 + BM - 1) return;
    const int kEnd = triK ? (m0 + BM) : K;
    const int nSteps = kEnd / BK;           // >= 8 for all our shapes

    const int t = threadIdx.x;
    const int lane = t & 31, warp = t >> 5;
    const int wm = warp >> 1;   // 0..3 -> 32 rows
    const int wn = warp & 1;    // 0..1 -> 64 cols

    float acc[2][8][4];
#pragma unroll
    for (int i = 0; i < 2; i++)
#pragma unroll
        for (int j = 0; j < 8; j++)
#pragma unroll
            for (int q = 0; q < 4; q++) acc[i][j][q] = 0.f;

    // fill one 16-k stage: 4 cp16 per thread (A hi/lo, B hi/lo)
    const int f_row = t >> 1;          // 0..127
    const int f_c16 = t & 1;           // 0..1
    const uint32_t f_so = swz_off(f_row, f_c16);
    auto fill = [&](int buf, int ks) {
        const uint32_t sb = smem_base + buf * STAGE;
        const long long g = (long long)f_row * K + ks * BK + f_c16 * 8;
        cp16(sb + 0 * SUB_B + f_so, Ah + (long long)m0 * K + g);
        cp16(sb + 1 * SUB_B + f_so, Al + (long long)m0 * K + g);
        cp16(sb + 2 * SUB_B + f_so, Bh + (long long)n0 * K + g);
        cp16(sb + 3 * SUB_B + f_so, Bl + (long long)n0 * K + g);
    };

    // ldmatrix lane->element mapping (validated since R2; only addressing swizzled)
    const int a_r = (lane & 7) + ((lane >> 3) & 1) * 8;
    const int a_h = lane >> 4;                 // col half 0/1
    const int b_r = (lane & 7) + ((lane >> 4) & 1) * 8;
    const int b_h = (lane >> 3) & 1;

    // prologue: 5 stages in flight
#pragma unroll
    for (int s = 0; s < 5; s++) {
        if (s < nSteps) fill(s, s);
        cp_commit();
    }

    int bufc = 0;        // c % 6
    int buff = 5;        // (c+5) % 6
    for (int c = 0; c < nSteps; c++) {
        cp_wait4();                 // group c complete
        __syncthreads();            // all warps past compute(c-1); buffer buff reusable

        if (c + 5 < nSteps) fill(buff, c + 5);
        cp_commit();

        const uint32_t sb = smem_base + bufc * STAGE;
        const uint32_t bAh = sb, bAl = sb + SUB_B;
        const uint32_t bBh = sb + 2 * SUB_B, bBl = sb + 3 * SUB_B;

        uint32_t ah[2][4], al[2][4];
#pragma unroll
        for (int mt = 0; mt < 2; mt++) {
            const int R = wm * 32 + mt * 16 + a_r;
            const uint32_t off = swz_off(R, a_h);
            ldsm4(ah[mt], bAh + off);
            ldsm4(al[mt], bAl + off);
        }
#pragma unroll
        for (int np = 0; np < 4; np++) {
            const int Rb = wn * 64 + np * 16 + b_r;
            const uint32_t off = swz_off(Rb, b_h);
            uint32_t bh[4], bl[4];
            ldsm4(bh, bBh + off);
            ldsm4(bl, bBl + off);
#pragma unroll
            for (int mt = 0; mt < 2; mt++) {
                mma16816(acc[mt][2 * np],     ah[mt], bh);
                mma16816(acc[mt][2 * np],     ah[mt], bl);
                mma16816(acc[mt][2 * np],     al[mt], bh);
                mma16816(acc[mt][2 * np + 1], ah[mt], bh + 2);
                mma16816(acc[mt][2 * np + 1], ah[mt], bl + 2);
                mma16816(acc[mt][2 * np + 1], al[mt], bh + 2);
            }
        }

        if (++bufc == NSTAGE) bufc = 0;
        if (++buff == NSTAGE) buff = 0;
    }

    // ---------------- epilogue ----------------
    if (EPI == 2) {
        cp_wait0();
        __syncthreads();
        bf16* Th = reinterpret_cast<bf16*>(dsm);              // [128][136]
        bf16* Tl = Th + 128 * 136;
#pragma unroll
        for (int mt = 0; mt < 2; mt++) {
            const int li0 = wm * 32 + mt * 16 + (lane >> 2);
#pragma unroll
            for (int nt = 0; nt < 8; nt++) {
                const int lj = wn * 64 + nt * 8 + (lane & 3) * 2;
#pragma unroll
                for (int h = 0; h < 2; h++) {
                    const int li = li0 + h * 8;
#pragma unroll
                    for (int cc = 0; cc < 2; cc++) {
                        float v = acc[mt][nt][h * 2 + cc];
                        if (bias) v += bias[n0 + lj + cc];
                        bf16 hh, ll;
                        split1(v, hh, ll);
                        Th[(lj + cc) * 136 + li] = hh;
                        Tl[(lj + cc) * 136 + li] = ll;
                    }
                }
            }
        }
        __syncthreads();
        {
            const int arr = t >> 7;          // 0 = hi, 1 = lo
            const int j = t & 127;           // local n (= d) row
            const int bb = m0 >> 11;         // SS = 2048
            const int s0 = m0 & (SS - 1);
            const bf16* src = (arr ? Tl : Th) + j * 136;
            bf16* dst = (arr ? Cl : Ch) + ((long long)bb * DD + n0 + j) * SS + s0;
#pragma unroll
            for (int i = 0; i < 128; i += 8)
                *reinterpret_cast<uint4*>(dst + i) =
                    *reinterpret_cast<const uint4*>(src + i);
        }
        return;
    }

#pragma unroll
    for (int mt = 0; mt < 2; mt++) {
        const int gi0 = m0 + wm * 32 + mt * 16 + (lane >> 2);
#pragma unroll
        for (int nt = 0; nt < 8; nt++) {
            const int gj = n0 + wn * 64 + nt * 8 + (lane & 3) * 2;
            const float* d = acc[mt][nt];
#pragma unroll
            for (int h = 0; h < 2; h++) {
                const int gi = gi0 + h * 8;
                float v0 = d[h * 2 + 0] * scale;
                float v1 = d[h * 2 + 1] * scale;
                if (bias) { v0 += bias[gj]; v1 += bias[gj + 1]; }
                if (causal) {
                    if (gj > gi) v0 = 0.f;
                    if (gj + 1 > gi) v1 = 0.f;
                }
                if (EPI == 0) {
                    *reinterpret_cast<float2*>(&C[(long long)gi * N + gj]) =
                        make_float2(v0, v1);
                } else {
                    bf16 h0, l0, h1, l1;
                    split1(v0, h0, l0);
                    split1(v1, h1, l1);
                    __nv_bfloat162 ph; ph.x = h0; ph.y = h1;
                    __nv_bfloat162 pl; pl.x = l0; pl.y = l1;
                    *reinterpret_cast<__nv_bfloat162*>(&Ch[(long long)gi * N + gj]) = ph;
                    *reinterpret_cast<__nv_bfloat162*>(&Cl[(long long)gi * N + gj]) = pl;
                }
            }
        }
    }
}

// ---------------------------------------------------------------------------
// Merged Q/K/V projection: grid z selects projection.
// ---------------------------------------------------------------------------
__global__ __launch_bounds__(256, 2) void proj3_kernel(
    const bf16* __restrict__ xh, const bf16* __restrict__ xl,
    const bf16* __restrict__ Wqh, const bf16* __restrict__ Wql,
    const float* __restrict__ bq, float* __restrict__ Q,
    const bf16* __restrict__ Wkh, const bf16* __restrict__ Wkl,
    const float* __restrict__ bk, float* __restrict__ Kt,
    const bf16* __restrict__ Wvh, const bf16* __restrict__ Wvl,
    const float* __restrict__ bv, bf16* __restrict__ Vth, bf16* __restrict__ Vtl)
{
    extern __shared__ __align__(128) char dsm[];
    const int m0 = blockIdx.y * BM;
    const int n0 = blockIdx.x * BN;
    const int z = blockIdx.z;
    if (z == 0)
        gemm_body<0>(xh, xl, Wqh, Wql, bq, Q, nullptr, nullptr,
                     DD, DD, 1.f, 0, 0, m0, n0, dsm);
    else if (z == 1)
        gemm_body<0>(xh, xl, Wkh, Wkl, bk, Kt, nullptr, nullptr,
                     DD, DD, 1.f, 0, 0, m0, n0, dsm);
    else
        gemm_body<2>(xh, xl, Wvh, Wvl, bv, nullptr, Vth, Vtl,
                     DD, DD, 1.f, 0, 0, m0, n0, dsm);
}

__global__ __launch_bounds__(256, 2) void scores_kernel(
    const bf16* __restrict__ Qh, const bf16* __restrict__ Ql,
    const bf16* __restrict__ Kh, const bf16* __restrict__ Kl,
    bf16* __restrict__ Ph, bf16* __restrict__ Pl, float scale)
{
    extern __shared__ __align__(128) char dsm[];
    const long long zd = (long long)blockIdx.z * SS * DD;
    const long long zs = (long long)blockIdx.z * SS * SS;
    gemm_body<1>(Qh + zd, Ql + zd, Kh + zd, Kl + zd, nullptr, nullptr,
                 Ph + zs, Pl + zs, SS, DD, scale, 1, 0,
                 blockIdx.y * BM, blockIdx.x * BN, dsm);
}

__global__ __launch_bounds__(256, 2) void pv_kernel(
    const bf16* __restrict__ Ph, const bf16* __restrict__ Pl,
    const bf16* __restrict__ Vth, const bf16* __restrict__ Vtl,
    bf16* __restrict__ Ch, bf16* __restrict__ Cl)
{
    extern __shared__ __align__(128) char dsm[];
    const long long zs = (long long)blockIdx.z * SS * SS;
    const long long zd = (long long)blockIdx.z * SS * DD;
    gemm_body<1>(Ph + zs, Pl + zs, Vth + zd, Vtl + zd, nullptr, nullptr,
                 Ch + zd, Cl + zd, DD, SS, 1.f, 0, 1,
                 blockIdx.y * BM, blockIdx.x * BN, dsm);
}

__global__ __launch_bounds__(256, 2) void outproj_kernel(
    const bf16* __restrict__ Ch, const bf16* __restrict__ Cl,
    const bf16* __restrict__ Woh, const bf16* __restrict__ Wol,
    const float* __restrict__ bo, float* __restrict__ out)
{
    extern __shared__ __align__(128) char dsm[];
    gemm_body<0>(Ch, Cl, Woh, Wol, bo, out, nullptr, nullptr,
                 DD, DD, 1.f, 0, 0, blockIdx.y * BM, blockIdx.x * BN, dsm);
}

// ---------------------------------------------------------------------------
// Fused split: x|Wq|Wk|Wv|Wo -> bf16 hi/lo in one launch; also fills invf.
// ---------------------------------------------------------------------------
constexpr long long N4X = (long long)BB * SS * DD / 4;
constexpr long long N4W = (long long)DD * DD / 4;

__global__ void split_all_kernel(
    const float* __restrict__ x,
    const float* __restrict__ Wq, const float* __restrict__ Wk,
    const float* __restrict__ Wv, const float* __restrict__ Wo,
    bf16* __restrict__ xh, bf16* __restrict__ xl,
    bf16* __restrict__ Wqh, bf16* __restrict__ Wql,
    bf16* __restrict__ Wkh, bf16* __restrict__ Wkl,
    bf16* __restrict__ Wvh, bf16* __restrict__ Wvl,
    bf16* __restrict__ Woh, bf16* __restrict__ Wol,
    float* __restrict__ invf)
{
    const long long i = (long long)blockIdx.x * blockDim.x + threadIdx.x;
    if (i < DD / 2)
        invf[i] = (float)exp(-(double)i * (9.210340371976184 / (double)(DD / 2)));

    const float* src;
    bf16 *dh, *dl;
    long long o = i;
    if (i < N4X)                { src = x;  dh = xh;  dl = xl; }
    else if (i < N4X + N4W)     { src = Wq; dh = Wqh; dl = Wql; o = i - N4X; }
    else if (i < N4X + 2 * N4W) { src = Wk; dh = Wkh; dl = Wkl; o = i - N4X - N4W; }
    else if (i < N4X + 3 * N4W) { src = Wv; dh = Wvh; dl = Wvl; o = i - N4X - 2 * N4W; }
    else if (i < N4X + 4 * N4W) { src = Wo; dh = Woh; dl = Wol; o = i - N4X - 3 * N4W; }
    else return;

    float4 v = *reinterpret_cast<const float4*>(src + o * 4);
    bf16 h[4], l[4];
    split1(v.x, h[0], l[0]); split1(v.y, h[1], l[1]);
    split1(v.z, h[2], l[2]); split1(v.w, h[3], l[3]);
    *reinterpret_cast<uint2*>(dh + o * 4) = *reinterpret_cast<uint2*>(h);
    *reinterpret_cast<uint2*>(dl + o * 4) = *reinterpret_cast<uint2*>(l);
}

// ---------------------------------------------------------------------------
// RoPE: rotate fp32 Q/K pairs, emit bf16 hi/lo splits.
// ---------------------------------------------------------------------------
__global__ void rope_split_kernel(const float* __restrict__ Q,
                                  const float* __restrict__ Kt,
                                  const float* __restrict__ invf,
                                  bf16* __restrict__ Qh, bf16* __restrict__ Ql,
                                  bf16* __restrict__ Kh, bf16* __restrict__ Kl)
{
    const int half = DD / 2;
    long long idx = (long long)blockIdx.x * blockDim.x + threadIdx.x;
    const long long total = (long long)BB * SS * half;
    if (idx >= total) return;

    const int i = (int)(idx % half);
    const long long bs = idx / half;
    const int s = (int)(bs % SS);

    const float ang = (float)s * invf[i];
    float sn, cs;
    sincosf(ang, &sn, &cs);

    const long long o = bs * DD;
    const float q1 = Q[o + i], q2 = Q[o + i + half];
    const float k1 = Kt[o + i], k2 = Kt[o + i + half];
    const float qa = q1 * cs - q2 * sn, qb = q1 * sn + q2 * cs;
    const float ka = k1 * cs - k2 * sn, kb = k1 * sn + k2 * cs;

    bf16 h, l;
    split1(qa, h, l); Qh[o + i] = h;        Ql[o + i] = l;
    split1(qb, h, l); Qh[o + i + half] = h; Ql[o + i + half] = l;
    split1(ka, h, l); Kh[o + i] = h;        Kl[o + i] = l;
    split1(kb, h, l); Kh[o + i + half] = h; Kl[o + i + half] = l;
}

// ---------------------------------------------------------------------------
// Register-resident causal softmax over split-bf16 scores (in place).
// ---------------------------------------------------------------------------
__inline__ __device__ float warpMax(float v)
{
    for (int o = 16; o; o >>= 1) v = fmaxf(v, __shfl_xor_sync(0xffffffffu, v, o));
    return v;
}
__inline__ __device__ float warpSum(float v)
{
    for (int o = 16; o; o >>= 1) v += __shfl_xor_sync(0xffffffffu, v, o);
    return v;
}

__global__ __launch_bounds__(256) void softmax_split_kernel(
    bf16* __restrict__ Ph, bf16* __restrict__ Pl)
{
    const int i = blockIdx.x;
    const int b = blockIdx.y;
    const long long off = ((long long)b * SS + i) * SS;
    const int len = i + 1;
    const int t = threadIdx.x;
    const int lane = t & 31, w = t >> 5;

    __shared__ float sh[8];
    __shared__ float s_bcast;

    float s[8];
    float m = -INFINITY;
#pragma unroll
    for (int p = 0; p < 8; p++) {
        const int j = t + p * 256;
        if (j < len) {
            s[p] = __bfloat162float(Ph[off + j]) + __bfloat162float(Pl[off + j]);
            m = fmaxf(m, s[p]);
        }
    }
    m = warpMax(m);
    if (lane == 0) sh[w] = m;
    __syncthreads();
    if (t == 0) {
        float mm = sh[0];
        for (int k = 1; k < 8; k++) mm = fmaxf(mm, sh[k]);
        s_bcast = mm;
    }
    __syncthreads();
    m = s_bcast;
    __syncthreads();

    float sum = 0.f;
#pragma unroll
    for (int p = 0; p < 8; p++) {
        const int j = t + p * 256;
        if (j < len) {
            s[p] = expf(s[p] - m);
            sum += s[p];
        }
    }
    sum = warpSum(sum);
    if (lane == 0) sh[w] = sum;
    __syncthreads();
    if (t == 0) {
        float ss = 0.f;
        for (int k = 0; k < 8; k++) ss += sh[k];
        s_bcast = ss;
    }
    __syncthreads();
    const float inv = 1.f / s_bcast;

#pragma unroll
    for (int p = 0; p < 8; p++) {
        const int j = t + p * 256;
        if (j < len) {
            bf16 h, l;
            split1(s[p] * inv, h, l);
            Ph[off + j] = h;
            Pl[off + j] = l;
        }
    }
}

// ---------------------------------------------------------------------------
extern "C" void kernel_launch(void* const* d_in, const int* in_sizes, int n_in,
                              void* d_out, int out_size)
{
    const float* x  = (const float*)d_in[0];
    // d_in[1] = mask — analytic
    const float* Wq = (const float*)d_in[2];
    const float* bq = (const float*)d_in[3];
    const float* Wk = (const float*)d_in[4];
    const float* bk = (const float*)d_in[5];
    const float* Wv = (const float*)d_in[6];
    const float* bv = (const float*)d_in[7];
    const float* Wo = (const float*)d_in[8];
    const float* bo = (const float*)d_in[9];
    float* out = (float*)d_out;

    float *pQ, *pK, *pInvf;
    cudaGetSymbolAddress((void**)&pQ, g_Q);
    cudaGetSymbolAddress((void**)&pK, g_K);
    cudaGetSymbolAddress((void**)&pInvf, g_invf);

    bf16 *xh, *xl, *Wqh, *Wql, *Wkh, *Wkl, *Wvh, *Wvl, *Woh, *Wol;
    bf16 *Qh, *Ql, *Kh, *Kl, *Vth, *Vtl, *Ph, *Pl, *Chh, *Cll;
    cudaGetSymbolAddress((void**)&xh, g_xh);   cudaGetSymbolAddress((void**)&xl, g_xl);
    cudaGetSymbolAddress((void**)&Wqh, g_Wqh); cudaGetSymbolAddress((void**)&Wql, g_Wql);
    cudaGetSymbolAddress((void**)&Wkh, g_Wkh); cudaGetSymbolAddress((void**)&Wkl, g_Wkl);
    cudaGetSymbolAddress((void**)&Wvh, g_Wvh); cudaGetSymbolAddress((void**)&Wvl, g_Wvl);
    cudaGetSymbolAddress((void**)&Woh, g_Woh); cudaGetSymbolAddress((void**)&Wol, g_Wol);
    cudaGetSymbolAddress((void**)&Qh, g_Qh);   cudaGetSymbolAddress((void**)&Ql, g_Ql);
    cudaGetSymbolAddress((void**)&Kh, g_Kh);   cudaGetSymbolAddress((void**)&Kl, g_Kl);
    cudaGetSymbolAddress((void**)&Vth, g_Vth); cudaGetSymbolAddress((void**)&Vtl, g_Vtl);
    cudaGetSymbolAddress((void**)&Ph, g_Ph);   cudaGetSymbolAddress((void**)&Pl, g_Pl);
    cudaGetSymbolAddress((void**)&Chh, g_Ch);  cudaGetSymbolAddress((void**)&Cll, g_Cl);

    cudaFuncSetAttribute(proj3_kernel,   cudaFuncAttributeMaxDynamicSharedMemorySize, SMEM_TOTAL);
    cudaFuncSetAttribute(scores_kernel,  cudaFuncAttributeMaxDynamicSharedMemorySize, SMEM_TOTAL);
    cudaFuncSetAttribute(pv_kernel,      cudaFuncAttributeMaxDynamicSharedMemorySize, SMEM_TOTAL);
    cudaFuncSetAttribute(outproj_kernel, cudaFuncAttributeMaxDynamicSharedMemorySize, SMEM_TOTAL);

    const dim3 blk(256);

    // 1) fused split of x and all weights (+ invf table)
    {
        const long long n4 = N4X + 4 * N4W;
        split_all_kernel<<<(int)((n4 + 255) / 256), 256>>>(
            x, Wq, Wk, Wv, Wo, xh, xl, Wqh, Wql, Wkh, Wkl, Wvh, Wvl, Woh, Wol, pInvf);
    }

    // 2) merged Q/K/V projections
    proj3_kernel<<<dim3(DD / BN, (BB * SS) / BM, 3), blk, SMEM_TOTAL>>>(
        xh, xl, Wqh, Wql, bq, pQ, Wkh, Wkl, bk, pK, Wvh, Wvl, bv, Vth, Vtl);

    // 3) RoPE + split Q/K
    {
        const long long total = (long long)BB * SS * (DD / 2);
        rope_split_kernel<<<(int)((total + 255) / 256), 256>>>(pQ, pK, pInvf,
                                                               Qh, Ql, Kh, Kl);
    }

    // 4) scores = Q K^T / sqrt(D), causal -> split bf16 P
    const float scale = 0.022097086912079608f;  // 1/sqrt(2048)
    scores_kernel<<<dim3(SS / BN, SS / BM, BB), blk, SMEM_TOTAL>>>(
        Qh, Ql, Kh, Kl, Ph, Pl, scale);

    // 5) register softmax on split P (in place)
    softmax_split_kernel<<<dim3(SS, BB), 256>>>(Ph, Pl);

    // 6) ctx = P V (triangular K) -> split ctx
    pv_kernel<<<dim3(DD / BN, SS / BM, BB), blk, SMEM_TOTAL>>>(
        Ph, Pl, Vth, Vtl, Chh, Cll);

    // 7) out = ctx Wo^T + bo
    outproj_kernel<<<dim3(DD / BN, (BB * SS) / BM, 1), blk, SMEM_TOTAL>>>(
        Chh, Cll, Woh, Wol, bo, out);
}

// round 13
// speedup vs baseline: 1.8477x; 1.6430x over previous
#include <cuda_runtime.h>
#include <cuda_fp16.h>
#include <math.h>
#include <stdint.h>

#define BB 4
#define SS 2048
#define DD 2048
typedef __half f16;

constexpr int BM = 128, BN = 128, BK = 16;
constexpr int SUB_B = 128 * 32;             // one sub-tile: 128 rows x 16 f16 (32B), swizzled
constexpr int STAGE = 3 * SUB_B;            // Ah, Al, Bf = 12 KB
constexpr int NSTAGE = 8;
constexpr int PIPE_D = 7;                   // stages in flight
constexpr int SMEM_TOTAL = NSTAGE * STAGE;  // 98304 (2 CTAs/SM)

// ---------------------------------------------------------------------------
// Scratch (device globals — no allocations allowed)
// ---------------------------------------------------------------------------
__device__ float g_Q [(size_t)BB * SS * DD];
__device__ float g_K [(size_t)BB * SS * DD];
__device__ float g_invf[DD / 2];

// A-side operands: fp16 hi/lo split.  B-side operands: single fp16.
__device__ f16 g_xh [(size_t)BB * SS * DD], g_xl [(size_t)BB * SS * DD];
__device__ f16 g_Wqf[(size_t)DD * DD];
__device__ f16 g_Wkf[(size_t)DD * DD];
__device__ f16 g_Wvf[(size_t)DD * DD];
__device__ f16 g_Wof[(size_t)DD * DD];
__device__ f16 g_Qh [(size_t)BB * SS * DD], g_Ql [(size_t)BB * SS * DD];
__device__ f16 g_Kf [(size_t)BB * SS * DD];
__device__ f16 g_Vtf[(size_t)BB * SS * DD];                      // [b][d][s]
__device__ f16 g_Ph [(size_t)BB * SS * SS], g_Pl [(size_t)BB * SS * SS];
__device__ f16 g_Ch [(size_t)BB * SS * DD], g_Cl [(size_t)BB * SS * DD];

// ---------------------------------------------------------------------------
// helpers
// ---------------------------------------------------------------------------
__device__ __forceinline__ uint32_t smem_u32(const void* p)
{
    uint32_t a;
    asm("{ .reg .u64 t; cvta.to.shared.u64 t, %1; cvt.u32.u64 %0, t; }"
        : "=r"(a) : "l"(p));
    return a;
}
__device__ __forceinline__ void cp16(uint32_t saddr, const void* g)
{
    asm volatile("cp.async.cg.shared.global [%0], [%1], 16;" :: "r"(saddr), "l"(g));
}
__device__ __forceinline__ void cp_commit() { asm volatile("cp.async.commit_group;"); }
__device__ __forceinline__ void cp_waitD()  { asm volatile("cp.async.wait_group 6;"); }
__device__ __forceinline__ void cp_wait0()  { asm volatile("cp.async.wait_group 0;"); }

__device__ __forceinline__ void ldsm4(uint32_t* r, uint32_t addr)
{
    asm volatile("ldmatrix.sync.aligned.m8n8.x4.shared.b16 {%0,%1,%2,%3}, [%4];\n"
                 : "=r"(r[0]), "=r"(r[1]), "=r"(r[2]), "=r"(r[3]) : "r"(addr));
}
__device__ __forceinline__ void mma16816(float* d, const uint32_t* a, const uint32_t* b)
{
    asm volatile(
        "mma.sync.aligned.m16n8k16.row.col.f32.f16.f16.f32 "
        "{%0,%1,%2,%3}, {%4,%5,%6,%7}, {%8,%9}, {%0,%1,%2,%3};\n"
        : "+f"(d[0]), "+f"(d[1]), "+f"(d[2]), "+f"(d[3])
        : "r"(a[0]), "r"(a[1]), "r"(a[2]), "r"(a[3]), "r"(b[0]), "r"(b[1]));
}
__device__ __forceinline__ void splitf(float v, f16& h, f16& l)
{
    h = __float2half(v);
    l = __float2half(v - __half2float(h));
}

// Swizzled smem byte offset within one sub-tile (validated in R10).
__device__ __forceinline__ uint32_t swz_off(int r, int c16)
{
    return (uint32_t)(r * 32 + ((c16 ^ ((r >> 2) & 1)) << 4));
}

// ---------------------------------------------------------------------------
// 2-term fp16 GEMM body (256 thr, 2 CTAs/SM, 8-stage BK=16 cp.async):
//   C[m,n] = sum_k A[m,k]*B[n,k];  acc = Ah*Bf + Al*Bf.
// EPI: 0 = fp32 C (+bias/scale/causal-zero), 1 = split f16 (Ch,Cl),
//      2 = single f16 + transpose per batch (Vt), with bias.
// ---------------------------------------------------------------------------
template <int EPI>
__device__ __forceinline__ void gemm_body(
    const f16* __restrict__ Ah, const f16* __restrict__ Al,
    const f16* __restrict__ Bf,
    const float* __restrict__ bias, float* __restrict__ C,
    f16* __restrict__ Ch, f16* __restrict__ Cl,
    int N, int K, float scale, int causal, int triK,
    int m0, int n0, char* dsm)
{
    const uint32_t smem_base = smem_u32(dsm);

    if (causal && n0 > m0 + BM - 1) return;
    const int kEnd = triK ? (m0 + BM) : K;
    const int nSteps = kEnd / BK;           // >= 8 for all our shapes

    const int t = threadIdx.x;
    const int lane = t & 31, warp = t >> 5;
    const int wm = warp >> 1;   // 0..3 -> 32 rows
    const int wn = warp & 1;    // 0..1 -> 64 cols

    float acc[2][8][4];
#pragma unroll
    for (int i = 0; i < 2; i++)
#pragma unroll
        for (int j = 0; j < 8; j++)
#pragma unroll
            for (int q = 0; q < 4; q++) acc[i][j][q] = 0.f;

    // fill one 16-k stage: 3 cp16 per thread (A hi, A lo, B)
    const int f_row = t >> 1;          // 0..127
    const int f_c16 = t & 1;           // 0..1
    const uint32_t f_so = swz_off(f_row, f_c16);
    auto fill = [&](int buf, int ks) {
        const uint32_t sb = smem_base + buf * STAGE;
        const long long g = (long long)f_row * K + ks * BK + f_c16 * 8;
        cp16(sb + 0 * SUB_B + f_so, Ah + (long long)m0 * K + g);
        cp16(sb + 1 * SUB_B + f_so, Al + (long long)m0 * K + g);
        cp16(sb + 2 * SUB_B + f_so, Bf + (long long)n0 * K + g);
    };

    // ldmatrix lane->element mapping (validated since R2)
    const int a_r = (lane & 7) + ((lane >> 3) & 1) * 8;
    const int a_h = lane >> 4;                 // col half 0/1
    const int b_r = (lane & 7) + ((lane >> 4) & 1) * 8;
    const int b_h = (lane >> 3) & 1;

    // prologue: PIPE_D stages in flight
#pragma unroll
    for (int s = 0; s < PIPE_D; s++) {
        if (s < nSteps) fill(s, s);
        cp_commit();
    }

    int bufc = 0;            // c % NSTAGE
    int buff = PIPE_D;       // (c + PIPE_D) % NSTAGE
    for (int c = 0; c < nSteps; c++) {
        cp_waitD();                 // group c complete
        __syncthreads();            // all warps past compute(c-1); buffer buff reusable

        if (c + PIPE_D < nSteps) fill(buff, c + PIPE_D);
        cp_commit();

        const uint32_t sb = smem_base + bufc * STAGE;
        const uint32_t bAh = sb, bAl = sb + SUB_B, bBf = sb + 2 * SUB_B;

        uint32_t ah[2][4], al[2][4];
#pragma unroll
        for (int mt = 0; mt < 2; mt++) {
            const int R = wm * 32 + mt * 16 + a_r;
            const uint32_t off = swz_off(R, a_h);
            ldsm4(ah[mt], bAh + off);
            ldsm4(al[mt], bAl + off);
        }
#pragma unroll
        for (int np = 0; np < 4; np++) {
            const int Rb = wn * 64 + np * 16 + b_r;
            const uint32_t off = swz_off(Rb, b_h);
            uint32_t bf[4];
            ldsm4(bf, bBf + off);
#pragma unroll
            for (int mt = 0; mt < 2; mt++) {
                mma16816(acc[mt][2 * np],     ah[mt], bf);
                mma16816(acc[mt][2 * np],     al[mt], bf);
                mma16816(acc[mt][2 * np + 1], ah[mt], bf + 2);
                mma16816(acc[mt][2 * np + 1], al[mt], bf + 2);
            }
        }

        if (++bufc == NSTAGE) bufc = 0;
        if (++buff == NSTAGE) buff = 0;
    }

    // ---------------- epilogue ----------------
    if (EPI == 2) {
        cp_wait0();
        __syncthreads();
        f16* Th = reinterpret_cast<f16*>(dsm);                // [128][136]
#pragma unroll
        for (int mt = 0; mt < 2; mt++) {
            const int li0 = wm * 32 + mt * 16 + (lane >> 2);
#pragma unroll
            for (int nt = 0; nt < 8; nt++) {
                const int lj = wn * 64 + nt * 8 + (lane & 3) * 2;
#pragma unroll
                for (int h = 0; h < 2; h++) {
                    const int li = li0 + h * 8;
#pragma unroll
                    for (int cc = 0; cc < 2; cc++) {
                        float v = acc[mt][nt][h * 2 + cc];
                        if (bias) v += bias[n0 + lj + cc];
                        Th[(lj + cc) * 136 + li] = __float2half(v);
                    }
                }
            }
        }
        __syncthreads();
        {
            const int j = t & 127;           // local n (= d) row
            const int hf = t >> 7;           // which 64-element half of the row
            const int bb = m0 >> 11;         // SS = 2048
            const int s0 = m0 & (SS - 1);
            const f16* src = Th + j * 136 + hf * 64;
            f16* dst = Ch + ((long long)bb * DD + n0 + j) * SS + s0 + hf * 64;
#pragma unroll
            for (int i = 0; i < 64; i += 8)
                *reinterpret_cast<uint4*>(dst + i) =
                    *reinterpret_cast<const uint4*>(src + i);
        }
        return;
    }

#pragma unroll
    for (int mt = 0; mt < 2; mt++) {
        const int gi0 = m0 + wm * 32 + mt * 16 + (lane >> 2);
#pragma unroll
        for (int nt = 0; nt < 8; nt++) {
            const int gj = n0 + wn * 64 + nt * 8 + (lane & 3) * 2;
            const float* d = acc[mt][nt];
#pragma unroll
            for (int h = 0; h < 2; h++) {
                const int gi = gi0 + h * 8;
                float v0 = d[h * 2 + 0] * scale;
                float v1 = d[h * 2 + 1] * scale;
                if (bias) { v0 += bias[gj]; v1 += bias[gj + 1]; }
                if (causal) {
                    if (gj > gi) v0 = 0.f;
                    if (gj + 1 > gi) v1 = 0.f;
                }
                if (EPI == 0) {
                    *reinterpret_cast<float2*>(&C[(long long)gi * N + gj]) =
                        make_float2(v0, v1);
                } else {
                    f16 h0, l0, h1, l1;
                    splitf(v0, h0, l0);
                    splitf(v1, h1, l1);
                    __half2 ph; ph.x = h0; ph.y = h1;
                    __half2 pl; pl.x = l0; pl.y = l1;
                    *reinterpret_cast<__half2*>(&Ch[(long long)gi * N + gj]) = ph;
                    *reinterpret_cast<__half2*>(&Cl[(long long)gi * N + gj]) = pl;
                }
            }
        }
    }
}

// ---------------------------------------------------------------------------
// Merged Q/K/V projection: grid z selects projection.
// ---------------------------------------------------------------------------
__global__ __launch_bounds__(256, 2) void proj3_kernel(
    const f16* __restrict__ xh, const f16* __restrict__ xl,
    const f16* __restrict__ Wqf, const float* __restrict__ bq, float* __restrict__ Q,
    const f16* __restrict__ Wkf, const float* __restrict__ bk, float* __restrict__ Kt,
    const f16* __restrict__ Wvf, const float* __restrict__ bv,
    f16* __restrict__ Vtf)
{
    extern __shared__ __align__(128) char dsm[];
    const int m0 = blockIdx.y * BM;
    const int n0 = blockIdx.x * BN;
    const int z = blockIdx.z;
    if (z == 0)
        gemm_body<0>(xh, xl, Wqf, bq, Q, nullptr, nullptr,
                     DD, DD, 1.f, 0, 0, m0, n0, dsm);
    else if (z == 1)
        gemm_body<0>(xh, xl, Wkf, bk, Kt, nullptr, nullptr,
                     DD, DD, 1.f, 0, 0, m0, n0, dsm);
    else
        gemm_body<2>(xh, xl, Wvf, bv, nullptr, Vtf, nullptr,
                     DD, DD, 1.f, 0, 0, m0, n0, dsm);
}

__global__ __launch_bounds__(256, 2) void scores_kernel(
    const f16* __restrict__ Qh, const f16* __restrict__ Ql,
    const f16* __restrict__ Kf,
    f16* __restrict__ Ph, f16* __restrict__ Pl, float scale)
{
    extern __shared__ __align__(128) char dsm[];
    const long long zd = (long long)blockIdx.z * SS * DD;
    const long long zs = (long long)blockIdx.z * SS * SS;
    gemm_body<1>(Qh + zd, Ql + zd, Kf + zd, nullptr, nullptr,
                 Ph + zs, Pl + zs, SS, DD, scale, 1, 0,
                 blockIdx.y * BM, blockIdx.x * BN, dsm);
}

__global__ __launch_bounds__(256, 2) void pv_kernel(
    const f16* __restrict__ Ph, const f16* __restrict__ Pl,
    const f16* __restrict__ Vtf,
    f16* __restrict__ Ch, f16* __restrict__ Cl)
{
    extern __shared__ __align__(128) char dsm[];
    const long long zs = (long long)blockIdx.z * SS * SS;
    const long long zd = (long long)blockIdx.z * SS * DD;
    gemm_body<1>(Ph + zs, Pl + zs, Vtf + zd, nullptr, nullptr,
                 Ch + zd, Cl + zd, DD, SS, 1.f, 0, 1,
                 blockIdx.y * BM, blockIdx.x * BN, dsm);
}

__global__ __launch_bounds__(256, 2) void outproj_kernel(
    const f16* __restrict__ Ch, const f16* __restrict__ Cl,
    const f16* __restrict__ Wof,
    const float* __restrict__ bo, float* __restrict__ out)
{
    extern __shared__ __align__(128) char dsm[];
    gemm_body<0>(Ch, Cl, Wof, bo, out, nullptr, nullptr,
                 DD, DD, 1.f, 0, 0, blockIdx.y * BM, blockIdx.x * BN, dsm);
}

// ---------------------------------------------------------------------------
// Fused split: x -> f16 hi/lo, weights -> single f16; also fills invf.
// ---------------------------------------------------------------------------
constexpr long long N4X = (long long)BB * SS * DD / 4;
constexpr long long N4W = (long long)DD * DD / 4;

__global__ void split_all_kernel(
    const float* __restrict__ x,
    const float* __restrict__ Wq, const float* __restrict__ Wk,
    const float* __restrict__ Wv, const float* __restrict__ Wo,
    f16* __restrict__ xh, f16* __restrict__ xl,
    f16* __restrict__ Wqf, f16* __restrict__ Wkf,
    f16* __restrict__ Wvf, f16* __restrict__ Wof,
    float* __restrict__ invf)
{
    const long long i = (long long)blockIdx.x * blockDim.x + threadIdx.x;
    if (i < DD / 2)
        invf[i] = (float)exp(-(double)i * (9.210340371976184 / (double)(DD / 2)));

    if (i < N4X) {
        float4 v = *reinterpret_cast<const float4*>(x + i * 4);
        f16 h[4], l[4];
        splitf(v.x, h[0], l[0]); splitf(v.y, h[1], l[1]);
        splitf(v.z, h[2], l[2]); splitf(v.w, h[3], l[3]);
        *reinterpret_cast<uint2*>(xh + i * 4) = *reinterpret_cast<uint2*>(h);
        *reinterpret_cast<uint2*>(xl + i * 4) = *reinterpret_cast<uint2*>(l);
        return;
    }
    const float* src;
    f16* dst;
    long long o = i - N4X;
    if (o < N4W)          { src = Wq; dst = Wqf; }
    else if (o < 2 * N4W) { src = Wk; dst = Wkf; o -= N4W; }
    else if (o < 3 * N4W) { src = Wv; dst = Wvf; o -= 2 * N4W; }
    else if (o < 4 * N4W) { src = Wo; dst = Wof; o -= 3 * N4W; }
    else return;

    float4 v = *reinterpret_cast<const float4*>(src + o * 4);
    f16 h[4];
    h[0] = __float2half(v.x); h[1] = __float2half(v.y);
    h[2] = __float2half(v.z); h[3] = __float2half(v.w);
    *reinterpret_cast<uint2*>(dst + o * 4) = *reinterpret_cast<uint2*>(h);
}

// ---------------------------------------------------------------------------
// RoPE: rotate fp32 Q/K pairs; Q -> f16 hi/lo (A-side), K -> single f16 (B-side).
// ---------------------------------------------------------------------------
__global__ void rope_split_kernel(const float* __restrict__ Q,
                                  const float* __restrict__ Kt,
                                  const float* __restrict__ invf,
                                  f16* __restrict__ Qh, f16* __restrict__ Ql,
                                  f16* __restrict__ Kf)
{
    const int half = DD / 2;
    long long idx = (long long)blockIdx.x * blockDim.x + threadIdx.x;
    const long long total = (long long)BB * SS * half;
    if (idx >= total) return;

    const int i = (int)(idx % half);
    const long long bs = idx / half;
    const int s = (int)(bs % SS);

    const float ang = (float)s * invf[i];
    float sn, cs;
    sincosf(ang, &sn, &cs);

    const long long o = bs * DD;
    const float q1 = Q[o + i], q2 = Q[o + i + half];
    const float k1 = Kt[o + i], k2 = Kt[o + i + half];
    const float qa = q1 * cs - q2 * sn, qb = q1 * sn + q2 * cs;
    const float ka = k1 * cs - k2 * sn, kb = k1 * sn + k2 * cs;

    f16 h, l;
    splitf(qa, h, l); Qh[o + i] = h;        Ql[o + i] = l;
    splitf(qb, h, l); Qh[o + i + half] = h; Ql[o + i + half] = l;
    Kf[o + i] = __float2half(ka);
    Kf[o + i + half] = __float2half(kb);
}

// ---------------------------------------------------------------------------
// Register-resident causal softmax over split-f16 scores (in place).
// ---------------------------------------------------------------------------
__inline__ __device__ float warpMax(float v)
{
    for (int o = 16; o; o >>= 1) v = fmaxf(v, __shfl_xor_sync(0xffffffffu, v, o));
    return v;
}
__inline__ __device__ float warpSum(float v)
{
    for (int o = 16; o; o >>= 1) v += __shfl_xor_sync(0xffffffffu, v, o);
    return v;
}

__global__ __launch_bounds__(256) void softmax_split_kernel(
    f16* __restrict__ Ph, f16* __restrict__ Pl)
{
    const int i = blockIdx.x;
    const int b = blockIdx.y;
    const long long off = ((long long)b * SS + i) * SS;
    const int len = i + 1;
    const int t = threadIdx.x;
    const int lane = t & 31, w = t >> 5;

    __shared__ float sh[8];
    __shared__ float s_bcast;

    float s[8];
    float m = -INFINITY;
#pragma unroll
    for (int p = 0; p < 8; p++) {
        const int j = t + p * 256;
        if (j < len) {
            s[p] = __half2float(Ph[off + j]) + __half2float(Pl[off + j]);
            m = fmaxf(m, s[p]);
        }
    }
    m = warpMax(m);
    if (lane == 0) sh[w] = m;
    __syncthreads();
    if (t == 0) {
        float mm = sh[0];
        for (int k = 1; k < 8; k++) mm = fmaxf(mm, sh[k]);
        s_bcast = mm;
    }
    __syncthreads();
    m = s_bcast;
    __syncthreads();

    float sum = 0.f;
#pragma unroll
    for (int p = 0; p < 8; p++) {
        const int j = t + p * 256;
        if (j < len) {
            s[p] = expf(s[p] - m);
            sum += s[p];
        }
    }
    sum = warpSum(sum);
    if (lane == 0) sh[w] = sum;
    __syncthreads();
    if (t == 0) {
        float ss = 0.f;
        for (int k = 0; k < 8; k++) ss += sh[k];
        s_bcast = ss;
    }
    __syncthreads();
    const float inv = 1.f / s_bcast;

#pragma unroll
    for (int p = 0; p < 8; p++) {
        const int j = t + p * 256;
        if (j < len) {
            f16 h, l;
            splitf(s[p] * inv, h, l);
            Ph[off + j] = h;
            Pl[off + j] = l;
        }
    }
}

// ---------------------------------------------------------------------------
extern "C" void kernel_launch(void* const* d_in, const int* in_sizes, int n_in,
                              void* d_out, int out_size)
{
    const float* x  = (const float*)d_in[0];
    // d_in[1] = mask — analytic
    const float* Wq = (const float*)d_in[2];
    const float* bq = (const float*)d_in[3];
    const float* Wk = (const float*)d_in[4];
    const float* bk = (const float*)d_in[5];
    const float* Wv = (const float*)d_in[6];
    const float* bv = (const float*)d_in[7];
    const float* Wo = (const float*)d_in[8];
    const float* bo = (const float*)d_in[9];
    float* out = (float*)d_out;

    float *pQ, *pK, *pInvf;
    cudaGetSymbolAddress((void**)&pQ, g_Q);
    cudaGetSymbolAddress((void**)&pK, g_K);
    cudaGetSymbolAddress((void**)&pInvf, g_invf);

    f16 *xh, *xl, *Wqf, *Wkf, *Wvf, *Wof;
    f16 *Qh, *Ql, *Kf, *Vtf, *Ph, *Pl, *Chh, *Cll;
    cudaGetSymbolAddress((void**)&xh, g_xh);   cudaGetSymbolAddress((void**)&xl, g_xl);
    cudaGetSymbolAddress((void**)&Wqf, g_Wqf); cudaGetSymbolAddress((void**)&Wkf, g_Wkf);
    cudaGetSymbolAddress((void**)&Wvf, g_Wvf); cudaGetSymbolAddress((void**)&Wof, g_Wof);
    cudaGetSymbolAddress((void**)&Qh, g_Qh);   cudaGetSymbolAddress((void**)&Ql, g_Ql);
    cudaGetSymbolAddress((void**)&Kf, g_Kf);
    cudaGetSymbolAddress((void**)&Vtf, g_Vtf);
    cudaGetSymbolAddress((void**)&Ph, g_Ph);   cudaGetSymbolAddress((void**)&Pl, g_Pl);
    cudaGetSymbolAddress((void**)&Chh, g_Ch);  cudaGetSymbolAddress((void**)&Cll, g_Cl);

    cudaFuncSetAttribute(proj3_kernel,   cudaFuncAttributeMaxDynamicSharedMemorySize, SMEM_TOTAL);
    cudaFuncSetAttribute(scores_kernel,  cudaFuncAttributeMaxDynamicSharedMemorySize, SMEM_TOTAL);
    cudaFuncSetAttribute(pv_kernel,      cudaFuncAttributeMaxDynamicSharedMemorySize, SMEM_TOTAL);
    cudaFuncSetAttribute(outproj_kernel, cudaFuncAttributeMaxDynamicSharedMemorySize, SMEM_TOTAL);

    const dim3 blk(256);

    // 1) fused split of x and all weights (+ invf table)
    {
        const long long n4 = N4X + 4 * N4W;
        split_all_kernel<<<(int)((n4 + 255) / 256), 256>>>(
            x, Wq, Wk, Wv, Wo, xh, xl, Wqf, Wkf, Wvf, Wof, pInvf);
    }

    // 2) merged Q/K/V projections
    proj3_kernel<<<dim3(DD / BN, (BB * SS) / BM, 3), blk, SMEM_TOTAL>>>(
        xh, xl, Wqf, bq, pQ, Wkf, bk, pK, Wvf, bv, Vtf);

    // 3) RoPE + split Q / round K
    {
        const long long total = (long long)BB * SS * (DD / 2);
        rope_split_kernel<<<(int)((total + 255) / 256), 256>>>(pQ, pK, pInvf,
                                                               Qh, Ql, Kf);
    }

    // 4) scores = Q K^T / sqrt(D), causal -> split f16 P
    const float scale = 0.022097086912079608f;  // 1/sqrt(2048)
    scores_kernel<<<dim3(SS / BN, SS / BM, BB), blk, SMEM_TOTAL>>>(
        Qh, Ql, Kf, Ph, Pl, scale);

    // 5) register softmax on split P (in place)
    softmax_split_kernel<<<dim3(SS, BB), 256>>>(Ph, Pl);

    // 6) ctx = P V (triangular K) -> split ctx
    pv_kernel<<<dim3(DD / BN, SS / BM, BB), blk, SMEM_TOTAL>>>(
        Ph, Pl, Vtf, Chh, Cll);

    // 7) out = ctx Wo^T + bo
    outproj_kernel<<<dim3(DD / BN, (BB * SS) / BM, 1), blk, SMEM_TOTAL>>>(
        Chh, Cll, Wof, bo, out);
}